// round 11
// baseline (speedup 1.0000x reference)
#include <cuda_runtime.h>
#include <cuda_bf16.h>
#include <cstdint>

// ---------------------------------------------------------------------------
// RQ-spline coupling flow log-prob, fused. Stage-2 GEMM on tensor cores via
// warp-level mma.sync (m16n8k16 bf16, 3xBF16 split precision ~ fp32 accuracy).
// F=16, H1=H2=64, K=8, L=8, NBP=25.
//
// R10 -> R11: BLK 128 + XOR-swizzled 128B strides -> smem 105KB -> 2 CTAs/SM
// (phase decoupling vs barrier convoys); split accumulator chains (ILP 2->4).
// ---------------------------------------------------------------------------

#define BLK 128          // threads per CTA = rows per CTA (4 warps), 2 CTAs/SM

// B operand Wf^T, [l][n=256][k=64] bf16, hi & mid, XOR-swizzle baked in:
// element (n,k) stored at n*64 + ((k>>3) ^ (n&7))*8 + (k&7)
__device__ __align__(16) unsigned short g_Bhi[8 * 256 * 64];
__device__ __align__(16) unsigned short g_Bmid[8 * 256 * 64];
__device__ __align__(16) float g_bf[8 * 256];    // bias, padded t*32+p layout
__device__ float g_lc[8];

// ---------------- precompute: Wf = W2@Wout, transposed, bf16 hi/mid --------
__global__ void precompute_kernel(const float* __restrict__ W2,
                                  const float* __restrict__ b2,
                                  const float* __restrict__ Wout,
                                  const float* __restrict__ bout,
                                  const float* __restrict__ scale) {
    const int NWF = 8 * 256 * 64;
    const int NBF = 8 * 256;
    int idx = blockIdx.x * blockDim.x + threadIdx.x;
    if (idx < NWF) {
        int l = idx / 16384;
        int r = idx % 16384;
        int n = r / 64;             // padded output col: t*32 + p
        int k = r % 64;             // h1 index
        int t = n >> 5, p = n & 31;
        float v = 0.0f;
        if (p < 25) {
            int col = (2 * t + (l & 1)) * 25 + p;   // transformed feature 2t+(l&1)
            const float* w2row = W2 + l * 4096 + k * 64;
            const float* wo = Wout + l * 25600 + col;
            #pragma unroll 8
            for (int j = 0; j < 64; j++) v += w2row[j] * wo[j * 400];
        }
        __nv_bfloat16 h = __float2bfloat16_rn(v);
        float rm = v - __bfloat162float(h);
        __nv_bfloat16 m = __float2bfloat16_rn(rm);
        // bake XOR swizzle: 16B chunk (k>>3) -> (k>>3) ^ (n&7)
        int sidx = l * 16384 + n * 64 + (((k >> 3) ^ (n & 7)) << 3) + (k & 7);
        g_Bhi[sidx]  = __bfloat16_as_ushort(h);
        g_Bmid[sidx] = __bfloat16_as_ushort(m);
    } else if (idx < NWF + NBF) {
        int e = idx - NWF;
        int l = e / 256;
        int n = e % 256;
        int t = n >> 5, p = n & 31;
        float v = 0.0f;
        if (p < 25) {
            int col = (2 * t + (l & 1)) * 25 + p;
            const float* b2r = b2 + l * 64;
            const float* wo = Wout + l * 25600 + col;
            #pragma unroll 8
            for (int j = 0; j < 64; j++) v += b2r[j] * wo[j * 400];
            v += bout[l * 400 + col];
        }
        g_bf[e] = v;
    } else if (idx < NWF + NBF + 8) {
        int l = idx - NWF - NBF;
        float v = 0.0f;
        for (int f = 0; f < 16; f++) v += logf(fabsf(scale[l * 16 + f]));
        g_lc[l] = v;
    }
}

__device__ __forceinline__ float fast_tanh(float x) {
    float cx = fminf(fmaxf(x, -15.0f), 15.0f);
    float e = __expf(2.0f * cx);
    return __fdividef(e - 1.0f, e + 1.0f);
}
__device__ __forceinline__ float softplus_f(float t) {
    float r = __logf(1.0f + __expf(t));
    return (t > 20.0f) ? t : r;
}

__device__ __forceinline__ void mma_bf16(float& d0, float& d1, float& d2, float& d3,
                                         uint32_t a0, uint32_t a1, uint32_t a2, uint32_t a3,
                                         uint32_t b0, uint32_t b1) {
    asm volatile(
        "mma.sync.aligned.m16n8k16.row.col.f32.bf16.bf16.f32 "
        "{%0,%1,%2,%3}, {%4,%5,%6,%7}, {%8,%9}, {%0,%1,%2,%3};"
        : "+f"(d0), "+f"(d1), "+f"(d2), "+f"(d3)
        : "r"(a0), "r"(a1), "r"(a2), "r"(a3), "r"(b0), "r"(b1));
}

__device__ __forceinline__ void ldm_x4(uint32_t& r0, uint32_t& r1,
                                       uint32_t& r2, uint32_t& r3, uint32_t saddr) {
    asm volatile("ldmatrix.sync.aligned.m8n8.x4.shared.b16 {%0,%1,%2,%3}, [%4];"
                 : "=r"(r0), "=r"(r1), "=r"(r2), "=r"(r3) : "r"(saddr));
}

// ---------------- smem layout (bytes) ----------------
static constexpr int SM_W    = 0;                       // weights: 6656 B
static constexpr int SM_AHI  = 6656;                    // 128 rows x 128 B (swizzled)
static constexpr int SM_AMID = SM_AHI + BLK * 128;      // 16384 each
static constexpr int SM_BHI  = SM_AMID + BLK * 128;     // 256 rows x 128 B (swizzled)
static constexpr int SM_BMID = SM_BHI + 256 * 128;
static constexpr int SM_TOTAL = SM_BMID + 256 * 128;    // = 104960 B -> 2 CTAs/SM
// PAR (D bounce, 4 warps x 32 rows x 34 f32 = 17408 B) aliases the A region
// (32768 B, dead after fragment hoist; syncthreads makes it race-free).
static constexpr int SM_PAR  = SM_AHI;

__global__ __launch_bounds__(BLK, 2)
void flow_kernel(const float* __restrict__ x,
                 const float* __restrict__ W0g, const float* __restrict__ b0g,
                 const float* __restrict__ W1g, const float* __restrict__ b1g,
                 const float* __restrict__ scaleg, const float* __restrict__ shiftg,
                 float* __restrict__ out, int B) {
    extern __shared__ __align__(16) char smem[];
    const uint32_t smb = (uint32_t)__cvta_generic_to_shared(smem);

    float* sW0 = (float*)(smem + SM_W);   // 256
    float* sb0 = sW0 + 256;               // 16
    float* sW1 = sb0 + 16;                // 1024
    float* sb1 = sW1 + 1024;              // 64
    float* ssc = sb1 + 64;                // 16
    float* ssh = ssc + 16;                // 16
    float* sbf = ssh + 16;                // 256

    const int tid  = threadIdx.x;
    const int w    = tid >> 5;            // warp id (0..3)
    const int lane = tid & 31;
    const int row  = blockIdx.x * BLK + tid;
    const bool valid = row < B;

    // z split by feature parity: za[t]=feat 2t, zb[t]=feat 2t+1
    float za[8], zb[8];
    if (valid) {
        const float4* xr = (const float4*)(x + (size_t)row * 16);
        #pragma unroll
        for (int qq = 0; qq < 4; qq++) {
            float4 v = xr[qq];
            za[2 * qq] = v.x;     zb[2 * qq] = v.y;
            za[2 * qq + 1] = v.z; zb[2 * qq + 1] = v.w;
        }
    } else {
        #pragma unroll
        for (int t = 0; t < 8; t++) { za[t] = 0.0f; zb[t] = 0.0f; }
    }

    float logdet = 0.0f;

    #pragma unroll 1
    for (int l = 7; l >= 0; --l) {
        __syncthreads();   // protect smem (incl. aliased PAR/A) from previous layer

        // -------- stage small weights + B tiles into smem --------
        for (int i = tid; i < 256; i += BLK) sW0[i] = W0g[l * 256 + i];
        for (int i = tid; i < 1024; i += BLK) sW1[i] = W1g[l * 1024 + i];
        if (tid < 64) sb1[tid] = b1g[l * 64 + tid];
        if (tid < 16) {
            sb0[tid] = b0g[l * 16 + tid];
            ssc[tid] = scaleg[l * 16 + tid];
            ssh[tid] = shiftg[l * 16 + tid];
        }
        for (int i = tid; i < 256; i += BLK) sbf[i] = g_bf[l * 256 + i];
        for (int i = tid; i < 256; i += BLK) {
            // copy B row i (128 B = 8 uint4); swizzle already baked in
            const uint4* srcH = (const uint4*)(g_Bhi  + l * 16384) + i * 8;
            const uint4* srcM = (const uint4*)(g_Bmid + l * 16384) + i * 8;
            uint4* dstH = (uint4*)(smem + SM_BHI  + i * 128);
            uint4* dstM = (uint4*)(smem + SM_BMID + i * 128);
            #pragma unroll
            for (int c = 0; c < 8; c++) { dstH[c] = srcH[c]; dstM[c] = srcM[c]; }
        }
        __syncthreads();

        const int par = l & 1;

        // -------- stage 0: h0 = tanh(mz @ W0 + b0) --------
        float h0[16];
        #pragma unroll
        for (int j = 0; j < 16; ++j) {
            float a = sb0[j];
            #pragma unroll
            for (int t = 0; t < 8; ++t) {
                float zk = par ? za[t] : zb[t];     // kept parity = 1-par
                int fk = 2 * t + 1 - par;
                a += zk * sW0[fk * 16 + j];
            }
            h0[j] = fast_tanh(a);
        }

        // -------- stage 1: h1 = tanh(h0 @ W1 + b1) --------
        float h1[64];
        #pragma unroll
        for (int j = 0; j < 64; ++j) h1[j] = sb1[j];
        #pragma unroll
        for (int k = 0; k < 16; ++k) {
            float hk = h0[k];
            const float4* wr = (const float4*)(sW1 + k * 64);
            #pragma unroll
            for (int j4 = 0; j4 < 16; ++j4) {
                float4 wv = wr[j4];
                h1[4 * j4 + 0] += hk * wv.x;
                h1[4 * j4 + 1] += hk * wv.y;
                h1[4 * j4 + 2] += hk * wv.z;
                h1[4 * j4 + 3] += hk * wv.w;
            }
        }

        // -------- split h1 into bf16 hi/mid, store A rows (swizzled) --------
        {
            uint32_t packH[32], packM[32];
            #pragma unroll
            for (int i = 0; i < 32; ++i) {
                float v0 = fast_tanh(h1[2 * i]);
                float v1 = fast_tanh(h1[2 * i + 1]);
                __nv_bfloat16 h0b = __float2bfloat16_rn(v0);
                __nv_bfloat16 h1b = __float2bfloat16_rn(v1);
                float r0 = v0 - __bfloat162float(h0b);
                float r1 = v1 - __bfloat162float(h1b);
                __nv_bfloat16 m0b = __float2bfloat16_rn(r0);
                __nv_bfloat16 m1b = __float2bfloat16_rn(r1);
                packH[i] = (uint32_t)__bfloat16_as_ushort(h0b) |
                           ((uint32_t)__bfloat16_as_ushort(h1b) << 16);
                packM[i] = (uint32_t)__bfloat16_as_ushort(m0b) |
                           ((uint32_t)__bfloat16_as_ushort(m1b) << 16);
            }
            // chunk c (16B, k=8c..8c+7) -> physical chunk c ^ (row&7)
            char* dhB = smem + SM_AHI  + tid * 128;
            char* dmB = smem + SM_AMID + tid * 128;
            int sx = tid & 7;
            #pragma unroll
            for (int c = 0; c < 8; c++) {
                int pc = (c ^ sx) * 16;
                *(uint4*)(dhB + pc) = make_uint4(packH[4*c], packH[4*c+1], packH[4*c+2], packH[4*c+3]);
                *(uint4*)(dmB + pc) = make_uint4(packM[4*c], packM[4*c+1], packM[4*c+2], packM[4*c+3]);
            }
        }
        __syncthreads();

        // -------- hoist A fragments via ldmatrix (2 m-tiles, 4 k-steps, hi+mid) --
        // lane -> row = 32w+16m+(lane&15); logical chunk = 2ks+(lane>>4); phys ^= row&7
        uint32_t Ah[2][4][4], Am[2][4][4];
        {
            uint32_t arow = (uint32_t)(lane & 15);
            uint32_t sx = arow & 7u;
            #pragma unroll
            for (int m = 0; m < 2; ++m) {
                uint32_t rbase = ((uint32_t)(32 * w + 16 * m) + arow) * 128u;
                #pragma unroll
                for (int ks = 0; ks < 4; ++ks) {
                    uint32_t pc = (((uint32_t)(2 * ks) + (uint32_t)(lane >> 4)) ^ sx) * 16u;
                    ldm_x4(Ah[m][ks][0], Ah[m][ks][1], Ah[m][ks][2], Ah[m][ks][3],
                           smb + SM_AHI + rbase + pc);
                    ldm_x4(Am[m][ks][0], Am[m][ks][1], Am[m][ks][2], Am[m][ks][3],
                           smb + SM_AMID + rbase + pc);
                }
            }
        }
        __syncthreads();   // all warps done reading A -> PAR aliasing now safe

        float* pwarp = (float*)(smem + SM_PAR + w * 4352);   // [32][34]

        // B-fragment lane terms: row offset lane&7, logical chunk lane>>3
        const uint32_t brow = (uint32_t)(lane & 7);
        const uint32_t bsx = brow;
        const uint32_t bc0 = (((uint32_t)(lane >> 3) + 0u) ^ bsx) * 16u;
        const uint32_t bc1 = (((uint32_t)(lane >> 3) + 4u) ^ bsx) * 16u;

        // -------- per transformed feature: mma + spline --------
        #pragma unroll 1
        for (int t = 0; t < 8; ++t) {
            #pragma unroll
            for (int j = 0; j < 4; ++j) {
                uint32_t nb = ((uint32_t)(t * 32 + 8 * j) + brow) * 128u;
                uint32_t Bh[4][2], Bm[4][2];
                ldm_x4(Bh[0][0], Bh[0][1], Bh[1][0], Bh[1][1], smb + SM_BHI + nb + bc0);
                ldm_x4(Bh[2][0], Bh[2][1], Bh[3][0], Bh[3][1], smb + SM_BHI + nb + bc1);
                ldm_x4(Bm[0][0], Bm[0][1], Bm[1][0], Bm[1][1], smb + SM_BMID + nb + bc0);
                ldm_x4(Bm[2][0], Bm[2][1], Bm[3][0], Bm[3][1], smb + SM_BMID + nb + bc1);

                #pragma unroll
                for (int m = 0; m < 2; ++m) {
                    // two independent half-chains (ks 0-1 / ks 2-3) -> ILP 4
                    float da0 = 0.0f, da1 = 0.0f, da2 = 0.0f, da3 = 0.0f;
                    float db0 = 0.0f, db1 = 0.0f, db2 = 0.0f, db3 = 0.0f;
                    #pragma unroll
                    for (int ks = 0; ks < 2; ++ks) {
                        mma_bf16(da0, da1, da2, da3,
                                 Ah[m][ks][0], Ah[m][ks][1], Ah[m][ks][2], Ah[m][ks][3],
                                 Bh[ks][0], Bh[ks][1]);
                        mma_bf16(da0, da1, da2, da3,
                                 Ah[m][ks][0], Ah[m][ks][1], Ah[m][ks][2], Ah[m][ks][3],
                                 Bm[ks][0], Bm[ks][1]);
                        mma_bf16(da0, da1, da2, da3,
                                 Am[m][ks][0], Am[m][ks][1], Am[m][ks][2], Am[m][ks][3],
                                 Bh[ks][0], Bh[ks][1]);
                    }
                    #pragma unroll
                    for (int ks = 2; ks < 4; ++ks) {
                        mma_bf16(db0, db1, db2, db3,
                                 Ah[m][ks][0], Ah[m][ks][1], Ah[m][ks][2], Ah[m][ks][3],
                                 Bh[ks][0], Bh[ks][1]);
                        mma_bf16(db0, db1, db2, db3,
                                 Ah[m][ks][0], Ah[m][ks][1], Ah[m][ks][2], Ah[m][ks][3],
                                 Bm[ks][0], Bm[ks][1]);
                        mma_bf16(db0, db1, db2, db3,
                                 Am[m][ks][0], Am[m][ks][1], Am[m][ks][2], Am[m][ks][3],
                                 Bh[ks][0], Bh[ks][1]);
                    }
                    float d0 = da0 + db0, d1 = da1 + db1;
                    float d2 = da2 + db2, d3 = da3 + db3;
                    // scatter D to padded params buffer (stride 34 -> 8B aligned)
                    int g = lane >> 2, q = lane & 3;
                    int r0 = 16 * m + g;
                    int c0 = 8 * j + 2 * q;
                    *(float2*)(pwarp + r0 * 34 + c0)       = make_float2(d0, d1);
                    *(float2*)(pwarp + (r0 + 8) * 34 + c0) = make_float2(d2, d3);
                }
            }
            __syncwarp();

            // gather this thread's row params + bias (float2)
            float acc[25];
            {
                const float2* pr = (const float2*)(pwarp + lane * 34);
                #pragma unroll
                for (int p = 0; p < 12; ++p) {
                    float2 v = pr[p];
                    acc[2 * p]     = v.x + sbf[t * 32 + 2 * p];
                    acc[2 * p + 1] = v.y + sbf[t * 32 + 2 * p + 1];
                }
                acc[24] = pwarp[lane * 34 + 24] + sbf[t * 32 + 24];
            }
            __syncwarp();   // params buffer free for next feature

            // ---- RQ spline forward + log-det ----
            float xv = par ? zb[t] : za[t];

            float mw = acc[0];
            #pragma unroll
            for (int k = 1; k < 8; ++k) mw = fmaxf(mw, acc[k]);
            float ew[8]; float swsum = 0.0f;
            #pragma unroll
            for (int k = 0; k < 8; ++k) { ew[k] = __expf(acc[k] - mw); swsum += ew[k]; }
            float cw = __fdividef(19.9992f, swsum);

            float mh = acc[8];
            #pragma unroll
            for (int k = 1; k < 8; ++k) mh = fmaxf(mh, acc[8 + k]);
            float eh[8]; float shsum = 0.0f;
            #pragma unroll
            for (int k = 0; k < 8; ++k) { eh[k] = __expf(acc[8 + k] - mh); shsum += eh[k]; }
            float chh = __fdividef(19.9992f, shsum);

            float cum = -10.0f, xk = -10.0f;
            int idx = 0;
            #pragma unroll
            for (int k = 0; k < 7; ++k) {
                cum += ew[k] * cw + 1e-4f;
                if (xv >= cum) { xk = cum; idx = k + 1; }
            }

            float yk = -10.0f, bh = 0.0f, bw = 1.0f, udk = 0.0f, udk1 = 0.0f;
            #pragma unroll
            for (int k = 0; k < 8; ++k) {
                float hh = eh[k] * chh + 1e-4f;
                if (k < idx) yk += hh;
                if (k == idx) {
                    bh = hh;
                    bw = ew[k] * cw + 1e-4f;
                    udk = acc[16 + k];
                    udk1 = acc[17 + k];
                }
            }

            float dk  = softplus_f(udk  + 0.54116665f) + 1e-4f;
            float dk1 = softplus_f(udk1 + 0.54116665f) + 1e-4f;
            float s   = __fdividef(bh, bw);
            float zt  = __saturatef(__fdividef(xv - xk, bw));
            float z1  = 1.0f - zt;
            float zz  = zt * zt;
            float zz1 = zt * z1;
            float den = s + (dk1 + dk - 2.0f * s) * zz1;
            float y   = yk + bh * __fdividef(s * zz + dk * zz1, den);
            float numld = dk1 * zz + 2.0f * s * zz1 + dk * z1 * z1;
            float ld = 2.0f * __logf(s) + __logf(numld) - 2.0f * __logf(den);

            bool outside = (xv <= -10.0f) || (xv >= 10.0f);
            if (outside) { y = xv; ld = 0.0f; }

            if (par) zb[t] = y; else za[t] = y;
            logdet += ld;
        }

        // -------- affine: z = z*scale + shift --------
        #pragma unroll
        for (int t = 0; t < 8; ++t) {
            za[t] = za[t] * ssc[2 * t]     + ssh[2 * t];
            zb[t] = zb[t] * ssc[2 * t + 1] + ssh[2 * t + 1];
        }
        logdet += g_lc[l];
    }

    float ss = 0.0f;
    #pragma unroll
    for (int t = 0; t < 8; ++t) ss += za[t] * za[t] + zb[t] * zb[t];

    if (valid) out[row] = -0.5f * ss - 14.703170f + logdet;   // 8*log(2*pi)
}

extern "C" void kernel_launch(void* const* d_in, const int* in_sizes, int n_in,
                              void* d_out, int out_size) {
    const float* x     = (const float*)d_in[0];
    const float* W0    = (const float*)d_in[1];
    const float* b0    = (const float*)d_in[2];
    const float* W1    = (const float*)d_in[3];
    const float* b1    = (const float*)d_in[4];
    const float* W2    = (const float*)d_in[5];
    const float* b2    = (const float*)d_in[6];
    const float* Wout  = (const float*)d_in[7];
    const float* bout  = (const float*)d_in[8];
    const float* scale = (const float*)d_in[9];
    const float* shift = (const float*)d_in[10];

    int B = in_sizes[0] / 16;

    const int NP = 8 * 256 * 64 + 8 * 256 + 8;
    precompute_kernel<<<(NP + 255) / 256, 256>>>(W2, b2, Wout, bout, scale);

    cudaFuncSetAttribute(flow_kernel, cudaFuncAttributeMaxDynamicSharedMemorySize, SM_TOTAL);
    flow_kernel<<<(B + BLK - 1) / BLK, BLK, SM_TOTAL>>>(
        x, W0, b0, W1, b1, scale, shift, (float*)d_out, B);
}

// round 12
// speedup vs baseline: 1.5567x; 1.5567x over previous
#include <cuda_runtime.h>
#include <cuda_bf16.h>
#include <cstdint>

// ---------------------------------------------------------------------------
// RQ-spline coupling flow log-prob, fused. Stage-1 AND stage-2 GEMMs on tensor
// cores via mma.sync m16n8k16 bf16 (3xBF16 split precision ~ fp32 accuracy).
// F=16, H1=H2=64, K=8, L=8, NBP=25.
//
// R11 -> R12: revert to BLK=384/1 CTA (R10 base). Stage-1 h0@W1 moved to
// tensor cores; its D-fragments convert in-register to stage-2 A-fragments
// (no A smem tile, no A ldmatrix). Only 2 __syncthreads per layer; h0/PAR
// buffers warp-local -> warps drift across phases (convoy fix).
// ---------------------------------------------------------------------------

#define BLK 384          // threads per CTA = rows per CTA (12 warps)

// B operand Wf^T, [l][n=256][k=64] bf16, hi & mid split parts
__device__ __align__(16) unsigned short g_Bhi[8 * 256 * 64];
__device__ __align__(16) unsigned short g_Bmid[8 * 256 * 64];
// W1^T, [l][n=64][k=16] bf16 hi/mid
__device__ __align__(16) unsigned short g_W1Thi[8 * 64 * 16];
__device__ __align__(16) unsigned short g_W1Tmid[8 * 64 * 16];
__device__ __align__(16) float g_bf[8 * 256];    // bias, padded t*32+p layout
__device__ float g_lc[8];

// ---------------- precompute ----------------
__global__ void precompute_kernel(const float* __restrict__ W1,
                                  const float* __restrict__ W2,
                                  const float* __restrict__ b2,
                                  const float* __restrict__ Wout,
                                  const float* __restrict__ bout,
                                  const float* __restrict__ scale) {
    const int NWF = 8 * 256 * 64;
    const int NBF = 8 * 256;
    const int NW1 = 8 * 64 * 16;
    int idx = blockIdx.x * blockDim.x + threadIdx.x;
    if (idx < NWF) {
        int l = idx / 16384;
        int r = idx % 16384;
        int n = r / 64;             // padded output col: t*32 + p
        int k = r % 64;             // h1 index
        int t = n >> 5, p = n & 31;
        float v = 0.0f;
        if (p < 25) {
            int col = (2 * t + (l & 1)) * 25 + p;   // transformed feature 2t+(l&1)
            const float* w2row = W2 + l * 4096 + k * 64;
            const float* wo = Wout + l * 25600 + col;
            #pragma unroll 8
            for (int j = 0; j < 64; j++) v += w2row[j] * wo[j * 400];
        }
        __nv_bfloat16 h = __float2bfloat16_rn(v);
        float rm = v - __bfloat162float(h);
        __nv_bfloat16 m = __float2bfloat16_rn(rm);
        g_Bhi[idx]  = __bfloat16_as_ushort(h);
        g_Bmid[idx] = __bfloat16_as_ushort(m);
    } else if (idx < NWF + NBF) {
        int e = idx - NWF;
        int l = e / 256;
        int n = e % 256;
        int t = n >> 5, p = n & 31;
        float v = 0.0f;
        if (p < 25) {
            int col = (2 * t + (l & 1)) * 25 + p;
            const float* b2r = b2 + l * 64;
            const float* wo = Wout + l * 25600 + col;
            #pragma unroll 8
            for (int j = 0; j < 64; j++) v += b2r[j] * wo[j * 400];
            v += bout[l * 400 + col];
        }
        g_bf[e] = v;
    } else if (idx < NWF + NBF + 8) {
        int l = idx - NWF - NBF;
        float v = 0.0f;
        for (int f = 0; f < 16; f++) v += logf(fabsf(scale[l * 16 + f]));
        g_lc[l] = v;
    } else if (idx < NWF + NBF + 8 + NW1) {
        int e = idx - NWF - NBF - 8;
        int l = e / 1024;
        int r = e % 1024;
        int n = r / 16;             // h1 col
        int k = r % 16;             // h0 index
        float v = W1[l * 1024 + k * 64 + n];
        __nv_bfloat16 h = __float2bfloat16_rn(v);
        float rm = v - __bfloat162float(h);
        __nv_bfloat16 m = __float2bfloat16_rn(rm);
        g_W1Thi[e]  = __bfloat16_as_ushort(h);
        g_W1Tmid[e] = __bfloat16_as_ushort(m);
    }
}

__device__ __forceinline__ float fast_tanh(float x) {
    float cx = fminf(fmaxf(x, -15.0f), 15.0f);
    float e = __expf(2.0f * cx);
    return __fdividef(e - 1.0f, e + 1.0f);
}
__device__ __forceinline__ float softplus_f(float t) {
    float r = __logf(1.0f + __expf(t));
    return (t > 20.0f) ? t : r;
}
__device__ __forceinline__ uint32_t pack_hi2(float v0, float v1) {
    return (uint32_t)__bfloat16_as_ushort(__float2bfloat16_rn(v0)) |
           ((uint32_t)__bfloat16_as_ushort(__float2bfloat16_rn(v1)) << 16);
}
__device__ __forceinline__ uint32_t pack_mid2(float v0, float v1) {
    float r0 = v0 - __bfloat162float(__float2bfloat16_rn(v0));
    float r1 = v1 - __bfloat162float(__float2bfloat16_rn(v1));
    return pack_hi2(r0, r1);
}

__device__ __forceinline__ void mma_bf16(float& d0, float& d1, float& d2, float& d3,
                                         uint32_t a0, uint32_t a1, uint32_t a2, uint32_t a3,
                                         uint32_t b0, uint32_t b1) {
    asm volatile(
        "mma.sync.aligned.m16n8k16.row.col.f32.bf16.bf16.f32 "
        "{%0,%1,%2,%3}, {%4,%5,%6,%7}, {%8,%9}, {%0,%1,%2,%3};"
        : "+f"(d0), "+f"(d1), "+f"(d2), "+f"(d3)
        : "r"(a0), "r"(a1), "r"(a2), "r"(a3), "r"(b0), "r"(b1));
}

__device__ __forceinline__ void ldm_x4(uint32_t& r0, uint32_t& r1,
                                       uint32_t& r2, uint32_t& r3, uint32_t saddr) {
    asm volatile("ldmatrix.sync.aligned.m8n8.x4.shared.b16 {%0,%1,%2,%3}, [%4];"
                 : "=r"(r0), "=r"(r1), "=r"(r2), "=r"(r3) : "r"(saddr));
}

// ---------------- smem layout (bytes) ----------------
static constexpr int SM_W     = 0;                      // small weights (2560 B)
static constexpr int SM_H0    = 2560;                   // 384 rows x 80 B (hi32|mid32|pad16)
static constexpr int SM_W1T   = SM_H0 + BLK * 80;       // = 33280; hi 64x48, mid +3072
static constexpr int SM_BHI   = SM_W1T + 6144;          // = 39424; 256 n x 144 B
static constexpr int SM_BMID  = SM_BHI + 256 * 144;     // = 76288
static constexpr int SM_PAR   = SM_BMID + 256 * 144;    // = 113152; 12 x 4352
static constexpr int SM_TOTAL = SM_PAR + 12 * 4352;     // = 165376 B (1 CTA/SM)

__global__ __launch_bounds__(BLK, 1)
void flow_kernel(const float* __restrict__ x,
                 const float* __restrict__ W0g, const float* __restrict__ b0g,
                 const float* __restrict__ b1g,
                 const float* __restrict__ scaleg, const float* __restrict__ shiftg,
                 float* __restrict__ out, int B) {
    extern __shared__ __align__(16) char smem[];
    const uint32_t smb = (uint32_t)__cvta_generic_to_shared(smem);

    float* sW0 = (float*)(smem + SM_W);   // 256
    float* sb0 = sW0 + 256;               // 16
    float* sb1 = sb0 + 16;                // 64
    float* ssc = sb1 + 64;                // 16
    float* ssh = ssc + 16;                // 16
    float* sbf = ssh + 16;                // 256

    const int tid  = threadIdx.x;
    const int w    = tid >> 5;            // warp id (0..11)
    const int lane = tid & 31;
    const int q    = lane & 3;
    const int row  = blockIdx.x * BLK + tid;
    const bool valid = row < B;

    // ldmatrix lane terms
    const uint32_t h0term = (uint32_t)(lane & 15) * 80u + (uint32_t)(lane >> 4) * 16u;
    const uint32_t w1term = ((uint32_t)(lane >> 4) * 8u + (uint32_t)(lane & 7)) * 48u
                          + (uint32_t)((lane >> 3) & 1) * 16u;
    const uint32_t bterm  = (uint32_t)(lane & 7) * 144u + (uint32_t)(lane >> 3) * 16u;

    // z split by feature parity: za[t]=feat 2t, zb[t]=feat 2t+1
    float za[8], zb[8];
    if (valid) {
        const float4* xr = (const float4*)(x + (size_t)row * 16);
        #pragma unroll
        for (int qq = 0; qq < 4; qq++) {
            float4 v = xr[qq];
            za[2 * qq] = v.x;     zb[2 * qq] = v.y;
            za[2 * qq + 1] = v.z; zb[2 * qq + 1] = v.w;
        }
    } else {
        #pragma unroll
        for (int t = 0; t < 8; t++) { za[t] = 0.0f; zb[t] = 0.0f; }
    }

    float logdet = 0.0f;

    #pragma unroll 1
    for (int l = 7; l >= 0; --l) {
        __syncthreads();   // all warps finished previous layer -> safe to restage

        // -------- stage small weights + W1T + B tiles into smem --------
        if (tid < 256) sW0[tid] = W0g[l * 256 + tid];
        if (tid < 64) sb1[tid] = b1g[l * 64 + tid];
        if (tid < 16) {
            sb0[tid] = b0g[l * 16 + tid];
            ssc[tid] = scaleg[l * 16 + tid];
            ssh[tid] = shiftg[l * 16 + tid];
        }
        if (tid < 256) sbf[tid] = g_bf[l * 256 + tid];
        if (tid >= 256 && tid < 320) {
            int i = tid - 256;     // W1T row i: 16 bf16 = 2 uint4 per part
            const uint4* srcH = (const uint4*)(g_W1Thi  + l * 1024 + i * 16);
            const uint4* srcM = (const uint4*)(g_W1Tmid + l * 1024 + i * 16);
            uint4* dstH = (uint4*)(smem + SM_W1T + i * 48);
            uint4* dstM = (uint4*)(smem + SM_W1T + 3072 + i * 48);
            dstH[0] = srcH[0]; dstH[1] = srcH[1];
            dstM[0] = srcM[0]; dstM[1] = srcM[1];
        }
        if (tid < 256) {
            // B row tid (64 bf16 = 8 uint4) for both parts
            const uint4* srcH = (const uint4*)(g_Bhi  + l * 16384) + tid * 8;
            const uint4* srcM = (const uint4*)(g_Bmid + l * 16384) + tid * 8;
            uint4* dstH = (uint4*)(smem + SM_BHI  + tid * 144);
            uint4* dstM = (uint4*)(smem + SM_BMID + tid * 144);
            #pragma unroll
            for (int c = 0; c < 8; c++) { dstH[c] = srcH[c]; dstM[c] = srcM[c]; }
        }
        __syncthreads();   // staging visible; warps free-run until next layer

        const int par = l & 1;

        // -------- stage 0: h0 = tanh(mz @ W0 + b0) (scalar, tiny) --------
        float h0[16];
        #pragma unroll
        for (int j = 0; j < 16; ++j) {
            float a = sb0[j];
            #pragma unroll
            for (int t = 0; t < 8; ++t) {
                float zk = par ? za[t] : zb[t];     // kept parity = 1-par
                int fk = 2 * t + 1 - par;
                a += zk * sW0[fk * 16 + j];
            }
            h0[j] = fast_tanh(a);
        }

        // -------- h0 -> warp-local bounce (bf16 hi/mid), then ldmatrix ------
        {
            uint32_t ph[8], pm[8];
            #pragma unroll
            for (int i = 0; i < 8; ++i) {
                ph[i] = pack_hi2(h0[2 * i], h0[2 * i + 1]);
                pm[i] = pack_mid2(h0[2 * i], h0[2 * i + 1]);
            }
            char* hb = smem + SM_H0 + tid * 80;
            *(uint4*)(hb)      = make_uint4(ph[0], ph[1], ph[2], ph[3]);
            *(uint4*)(hb + 16) = make_uint4(ph[4], ph[5], ph[6], ph[7]);
            *(uint4*)(hb + 32) = make_uint4(pm[0], pm[1], pm[2], pm[3]);
            *(uint4*)(hb + 48) = make_uint4(pm[4], pm[5], pm[6], pm[7]);
        }
        __syncwarp();

        uint32_t Ha[2][4], Ma[2][4];
        {
            uint32_t rb = SM_H0 + (uint32_t)(32 * w) * 80u + h0term;
            ldm_x4(Ha[0][0], Ha[0][1], Ha[0][2], Ha[0][3], smb + rb);
            ldm_x4(Ha[1][0], Ha[1][1], Ha[1][2], Ha[1][3], smb + rb + 16 * 80);
            ldm_x4(Ma[0][0], Ma[0][1], Ma[0][2], Ma[0][3], smb + rb + 32);
            ldm_x4(Ma[1][0], Ma[1][1], Ma[1][2], Ma[1][3], smb + rb + 16 * 80 + 32);
        }

        // -------- W1T fragments (hi/mid) --------
        uint32_t Wb[8][2], Wm[8][2];
        #pragma unroll
        for (int jj = 0; jj < 4; ++jj) {
            ldm_x4(Wb[2*jj][0], Wb[2*jj][1], Wb[2*jj+1][0], Wb[2*jj+1][1],
                   smb + SM_W1T + (uint32_t)(jj * 16 * 48) + w1term);
            ldm_x4(Wm[2*jj][0], Wm[2*jj][1], Wm[2*jj+1][0], Wm[2*jj+1][1],
                   smb + SM_W1T + 3072u + (uint32_t)(jj * 16 * 48) + w1term);
        }

        // bias pairs for this lane's columns
        float2 b1j[8];
        #pragma unroll
        for (int j = 0; j < 8; ++j) b1j[j] = *(float2*)(sb1 + 8 * j + 2 * q);

        // -------- stage 1 GEMM + tanh -> stage-2 A fragments in registers ----
        uint32_t Ah[2][4][4], Am[2][4][4];
        #pragma unroll
        for (int m = 0; m < 2; ++m) {
            float d[8][4];
            #pragma unroll
            for (int j = 0; j < 8; ++j) {
                d[j][0] = b1j[j].x; d[j][1] = b1j[j].y;
                d[j][2] = b1j[j].x; d[j][3] = b1j[j].y;
            }
            #pragma unroll
            for (int j = 0; j < 8; ++j) {
                mma_bf16(d[j][0], d[j][1], d[j][2], d[j][3],
                         Ha[m][0], Ha[m][1], Ha[m][2], Ha[m][3], Wb[j][0], Wb[j][1]);
                mma_bf16(d[j][0], d[j][1], d[j][2], d[j][3],
                         Ha[m][0], Ha[m][1], Ha[m][2], Ha[m][3], Wm[j][0], Wm[j][1]);
                mma_bf16(d[j][0], d[j][1], d[j][2], d[j][3],
                         Ma[m][0], Ma[m][1], Ma[m][2], Ma[m][3], Wb[j][0], Wb[j][1]);
            }
            // h1 = tanh(d); D-fragment == stage-2 A-fragment layout
            #pragma unroll
            for (int ks = 0; ks < 4; ++ks) {
                #pragma unroll
                for (int hh = 0; hh < 2; ++hh) {
                    int j = 2 * ks + hh;
                    float v0 = fast_tanh(d[j][0]);
                    float v1 = fast_tanh(d[j][1]);
                    float v2 = fast_tanh(d[j][2]);
                    float v3 = fast_tanh(d[j][3]);
                    Ah[m][ks][2 * hh]     = pack_hi2(v0, v1);
                    Ah[m][ks][2 * hh + 1] = pack_hi2(v2, v3);
                    Am[m][ks][2 * hh]     = pack_mid2(v0, v1);
                    Am[m][ks][2 * hh + 1] = pack_mid2(v2, v3);
                }
            }
        }

        float* pwarp = (float*)(smem + SM_PAR + w * 4352);   // [32][34], warp-local

        // -------- per transformed feature: stage-2 mma + spline --------
        #pragma unroll 1
        for (int t = 0; t < 8; ++t) {
            #pragma unroll
            for (int j = 0; j < 4; ++j) {
                uint32_t nb = (uint32_t)(t * 32 + 8 * j) * 144u + bterm;
                uint32_t Bh[4][2], Bm[4][2];
                ldm_x4(Bh[0][0], Bh[0][1], Bh[1][0], Bh[1][1], smb + SM_BHI + nb);
                ldm_x4(Bh[2][0], Bh[2][1], Bh[3][0], Bh[3][1], smb + SM_BHI + nb + 64u);
                ldm_x4(Bm[0][0], Bm[0][1], Bm[1][0], Bm[1][1], smb + SM_BMID + nb);
                ldm_x4(Bm[2][0], Bm[2][1], Bm[3][0], Bm[3][1], smb + SM_BMID + nb + 64u);

                #pragma unroll
                for (int m = 0; m < 2; ++m) {
                    // two independent half-chains (ks 0-1 / ks 2-3) -> ILP 4
                    float da0 = 0.0f, da1 = 0.0f, da2 = 0.0f, da3 = 0.0f;
                    float db0 = 0.0f, db1 = 0.0f, db2 = 0.0f, db3 = 0.0f;
                    #pragma unroll
                    for (int ks = 0; ks < 2; ++ks) {
                        mma_bf16(da0, da1, da2, da3,
                                 Ah[m][ks][0], Ah[m][ks][1], Ah[m][ks][2], Ah[m][ks][3],
                                 Bh[ks][0], Bh[ks][1]);
                        mma_bf16(da0, da1, da2, da3,
                                 Ah[m][ks][0], Ah[m][ks][1], Ah[m][ks][2], Ah[m][ks][3],
                                 Bm[ks][0], Bm[ks][1]);
                        mma_bf16(da0, da1, da2, da3,
                                 Am[m][ks][0], Am[m][ks][1], Am[m][ks][2], Am[m][ks][3],
                                 Bh[ks][0], Bh[ks][1]);
                    }
                    #pragma unroll
                    for (int ks = 2; ks < 4; ++ks) {
                        mma_bf16(db0, db1, db2, db3,
                                 Ah[m][ks][0], Ah[m][ks][1], Ah[m][ks][2], Ah[m][ks][3],
                                 Bh[ks][0], Bh[ks][1]);
                        mma_bf16(db0, db1, db2, db3,
                                 Ah[m][ks][0], Ah[m][ks][1], Ah[m][ks][2], Ah[m][ks][3],
                                 Bm[ks][0], Bm[ks][1]);
                        mma_bf16(db0, db1, db2, db3,
                                 Am[m][ks][0], Am[m][ks][1], Am[m][ks][2], Am[m][ks][3],
                                 Bh[ks][0], Bh[ks][1]);
                    }
                    float d0 = da0 + db0, d1 = da1 + db1;
                    float d2 = da2 + db2, d3 = da3 + db3;
                    int g = lane >> 2;
                    int r0 = 16 * m + g;
                    int c0 = 8 * j + 2 * q;
                    *(float2*)(pwarp + r0 * 34 + c0)       = make_float2(d0, d1);
                    *(float2*)(pwarp + (r0 + 8) * 34 + c0) = make_float2(d2, d3);
                }
            }
            __syncwarp();

            // gather this thread's row params + bias (float2)
            float acc[25];
            {
                const float2* pr = (const float2*)(pwarp + lane * 34);
                #pragma unroll
                for (int p = 0; p < 12; ++p) {
                    float2 v = pr[p];
                    acc[2 * p]     = v.x + sbf[t * 32 + 2 * p];
                    acc[2 * p + 1] = v.y + sbf[t * 32 + 2 * p + 1];
                }
                acc[24] = pwarp[lane * 34 + 24] + sbf[t * 32 + 24];
            }
            __syncwarp();   // params buffer free for next feature

            // ---- RQ spline forward + log-det ----
            float xv = par ? zb[t] : za[t];

            float mw = acc[0];
            #pragma unroll
            for (int k = 1; k < 8; ++k) mw = fmaxf(mw, acc[k]);
            float ew[8]; float swsum = 0.0f;
            #pragma unroll
            for (int k = 0; k < 8; ++k) { ew[k] = __expf(acc[k] - mw); swsum += ew[k]; }
            float cw = __fdividef(19.9992f, swsum);

            float mh = acc[8];
            #pragma unroll
            for (int k = 1; k < 8; ++k) mh = fmaxf(mh, acc[8 + k]);
            float eh[8]; float shsum = 0.0f;
            #pragma unroll
            for (int k = 0; k < 8; ++k) { eh[k] = __expf(acc[8 + k] - mh); shsum += eh[k]; }
            float chh = __fdividef(19.9992f, shsum);

            float cum = -10.0f, xk = -10.0f;
            int idx = 0;
            #pragma unroll
            for (int k = 0; k < 7; ++k) {
                cum += ew[k] * cw + 1e-4f;
                if (xv >= cum) { xk = cum; idx = k + 1; }
            }

            float yk = -10.0f, bh = 0.0f, bw = 1.0f, udk = 0.0f, udk1 = 0.0f;
            #pragma unroll
            for (int k = 0; k < 8; ++k) {
                float hh = eh[k] * chh + 1e-4f;
                if (k < idx) yk += hh;
                if (k == idx) {
                    bh = hh;
                    bw = ew[k] * cw + 1e-4f;
                    udk = acc[16 + k];
                    udk1 = acc[17 + k];
                }
            }

            float dk  = softplus_f(udk  + 0.54116665f) + 1e-4f;
            float dk1 = softplus_f(udk1 + 0.54116665f) + 1e-4f;
            float s   = __fdividef(bh, bw);
            float zt  = __saturatef(__fdividef(xv - xk, bw));
            float z1  = 1.0f - zt;
            float zz  = zt * zt;
            float zz1 = zt * z1;
            float den = s + (dk1 + dk - 2.0f * s) * zz1;
            float y   = yk + bh * __fdividef(s * zz + dk * zz1, den);
            float numld = dk1 * zz + 2.0f * s * zz1 + dk * z1 * z1;
            float ld = 2.0f * __logf(s) + __logf(numld) - 2.0f * __logf(den);

            bool outside = (xv <= -10.0f) || (xv >= 10.0f);
            if (outside) { y = xv; ld = 0.0f; }

            if (par) zb[t] = y; else za[t] = y;
            logdet += ld;
        }

        // -------- affine: z = z*scale + shift --------
        #pragma unroll
        for (int t = 0; t < 8; ++t) {
            za[t] = za[t] * ssc[2 * t]     + ssh[2 * t];
            zb[t] = zb[t] * ssc[2 * t + 1] + ssh[2 * t + 1];
        }
        logdet += g_lc[l];
    }

    float ss = 0.0f;
    #pragma unroll
    for (int t = 0; t < 8; ++t) ss += za[t] * za[t] + zb[t] * zb[t];

    if (valid) out[row] = -0.5f * ss - 14.703170f + logdet;   // 8*log(2*pi)
}

extern "C" void kernel_launch(void* const* d_in, const int* in_sizes, int n_in,
                              void* d_out, int out_size) {
    const float* x     = (const float*)d_in[0];
    const float* W0    = (const float*)d_in[1];
    const float* b0    = (const float*)d_in[2];
    const float* W1    = (const float*)d_in[3];
    const float* b1    = (const float*)d_in[4];
    const float* W2    = (const float*)d_in[5];
    const float* b2    = (const float*)d_in[6];
    const float* Wout  = (const float*)d_in[7];
    const float* bout  = (const float*)d_in[8];
    const float* scale = (const float*)d_in[9];
    const float* shift = (const float*)d_in[10];

    int B = in_sizes[0] / 16;

    const int NP = 8 * 256 * 64 + 8 * 256 + 8 + 8 * 64 * 16;
    precompute_kernel<<<(NP + 255) / 256, 256>>>(W1, W2, b2, Wout, bout, scale);

    cudaFuncSetAttribute(flow_kernel, cudaFuncAttributeMaxDynamicSharedMemorySize, SM_TOTAL);
    flow_kernel<<<(B + BLK - 1) / BLK, BLK, SM_TOTAL>>>(
        x, W0, b0, b1, scale, shift, (float*)d_out, B);
}

// round 15
// speedup vs baseline: 2.5219x; 1.6201x over previous
#include <cuda_runtime.h>
#include <cuda_bf16.h>
#include <cuda_fp16.h>
#include <cstdint>

// ---------------------------------------------------------------------------
// RQ-spline coupling flow log-prob, fused. Stage-1 AND stage-2 GEMMs on tensor
// cores via mma.sync m16n8k16 **fp16 single-pass** (error ~2^-11, well under
// the 1e-3 threshold; the accuracy floor is fast-math exp/log anyway).
// F=16, H1=H2=64, K=8, L=8, NBP=25.
//
// R13 resubmit (prior bench died in the GB300 broker, no kernel signal):
// 3xBF16 split -> 1xFP16 (HMMA count -66%, B traffic halved), BLK 384 -> 512
// (16 warps/SM with the freed registers).
// ---------------------------------------------------------------------------

#define BLK 512          // threads per CTA = rows per CTA (16 warps)

// B operand Wf^T, [l][n=256][k=64] fp16
__device__ __align__(16) unsigned short g_Bh[8 * 256 * 64];
// W1^T, [l][n=64][k=16] fp16
__device__ __align__(16) unsigned short g_W1T[8 * 64 * 16];
__device__ __align__(16) float g_bf[8 * 256];    // bias, padded t*32+p layout
__device__ float g_lc[8];

// ---------------- precompute ----------------
__global__ void precompute_kernel(const float* __restrict__ W1,
                                  const float* __restrict__ W2,
                                  const float* __restrict__ b2,
                                  const float* __restrict__ Wout,
                                  const float* __restrict__ bout,
                                  const float* __restrict__ scale) {
    const int NWF = 8 * 256 * 64;
    const int NBF = 8 * 256;
    const int NW1 = 8 * 64 * 16;
    int idx = blockIdx.x * blockDim.x + threadIdx.x;
    if (idx < NWF) {
        int l = idx / 16384;
        int r = idx % 16384;
        int n = r / 64;             // padded output col: t*32 + p
        int k = r % 64;             // h1 index
        int t = n >> 5, p = n & 31;
        float v = 0.0f;
        if (p < 25) {
            int col = (2 * t + (l & 1)) * 25 + p;   // transformed feature 2t+(l&1)
            const float* w2row = W2 + l * 4096 + k * 64;
            const float* wo = Wout + l * 25600 + col;
            #pragma unroll 8
            for (int j = 0; j < 64; j++) v += w2row[j] * wo[j * 400];
        }
        g_Bh[idx] = __half_as_ushort(__float2half_rn(v));
    } else if (idx < NWF + NBF) {
        int e = idx - NWF;
        int l = e / 256;
        int n = e % 256;
        int t = n >> 5, p = n & 31;
        float v = 0.0f;
        if (p < 25) {
            int col = (2 * t + (l & 1)) * 25 + p;
            const float* b2r = b2 + l * 64;
            const float* wo = Wout + l * 25600 + col;
            #pragma unroll 8
            for (int j = 0; j < 64; j++) v += b2r[j] * wo[j * 400];
            v += bout[l * 400 + col];
        }
        g_bf[e] = v;
    } else if (idx < NWF + NBF + 8) {
        int l = idx - NWF - NBF;
        float v = 0.0f;
        for (int f = 0; f < 16; f++) v += logf(fabsf(scale[l * 16 + f]));
        g_lc[l] = v;
    } else if (idx < NWF + NBF + 8 + NW1) {
        int e = idx - NWF - NBF - 8;
        int l = e / 1024;
        int r = e % 1024;
        int n = r / 16;             // h1 col
        int k = r % 16;             // h0 index
        float v = W1[l * 1024 + k * 64 + n];
        g_W1T[e] = __half_as_ushort(__float2half_rn(v));
    }
}

__device__ __forceinline__ float fast_tanh(float x) {
    float cx = fminf(fmaxf(x, -15.0f), 15.0f);
    float e = __expf(2.0f * cx);
    return __fdividef(e - 1.0f, e + 1.0f);
}
__device__ __forceinline__ float softplus_f(float t) {
    float r = __logf(1.0f + __expf(t));
    return (t > 20.0f) ? t : r;
}
__device__ __forceinline__ uint32_t pack_h2(float v0, float v1) {
    __half2 h = __floats2half2_rn(v0, v1);
    return *reinterpret_cast<uint32_t*>(&h);
}

__device__ __forceinline__ void mma_f16(float& d0, float& d1, float& d2, float& d3,
                                        uint32_t a0, uint32_t a1, uint32_t a2, uint32_t a3,
                                        uint32_t b0, uint32_t b1) {
    asm volatile(
        "mma.sync.aligned.m16n8k16.row.col.f32.f16.f16.f32 "
        "{%0,%1,%2,%3}, {%4,%5,%6,%7}, {%8,%9}, {%0,%1,%2,%3};"
        : "+f"(d0), "+f"(d1), "+f"(d2), "+f"(d3)
        : "r"(a0), "r"(a1), "r"(a2), "r"(a3), "r"(b0), "r"(b1));
}

__device__ __forceinline__ void ldm_x4(uint32_t& r0, uint32_t& r1,
                                       uint32_t& r2, uint32_t& r3, uint32_t saddr) {
    asm volatile("ldmatrix.sync.aligned.m8n8.x4.shared.b16 {%0,%1,%2,%3}, [%4];"
                 : "=r"(r0), "=r"(r1), "=r"(r2), "=r"(r3) : "r"(saddr));
}

// ---------------- smem layout (bytes) ----------------
static constexpr int SM_W     = 0;                      // small weights (2560 B)
static constexpr int SM_H0    = 2560;                   // BLK rows x 48 B (32B data)
static constexpr int SM_W1T   = SM_H0 + BLK * 48;       // 64 x 48 B = 3072
static constexpr int SM_BH    = SM_W1T + 3072;          // 256 n x 144 B (128B data)
static constexpr int SM_PAR   = SM_BH + 256 * 144;      // 16 warps x 4352 B
static constexpr int SM_TOTAL = SM_PAR + (BLK / 32) * 4352;   // = 136704 B

__global__ __launch_bounds__(BLK, 1)
void flow_kernel(const float* __restrict__ x,
                 const float* __restrict__ W0g, const float* __restrict__ b0g,
                 const float* __restrict__ b1g,
                 const float* __restrict__ scaleg, const float* __restrict__ shiftg,
                 float* __restrict__ out, int B) {
    extern __shared__ __align__(16) char smem[];
    const uint32_t smb = (uint32_t)__cvta_generic_to_shared(smem);

    float* sW0 = (float*)(smem + SM_W);   // 256
    float* sb0 = sW0 + 256;               // 16
    float* sb1 = sb0 + 16;                // 64
    float* ssc = sb1 + 64;                // 16
    float* ssh = ssc + 16;                // 16
    float* sbf = ssh + 16;                // 256

    const int tid  = threadIdx.x;
    const int w    = tid >> 5;            // warp id (0..15)
    const int lane = tid & 31;
    const int q    = lane & 3;
    const int row  = blockIdx.x * BLK + tid;
    const bool valid = row < B;

    // ldmatrix lane terms
    const uint32_t h0term = (uint32_t)(lane & 15) * 48u + (uint32_t)(lane >> 4) * 16u;
    const uint32_t w1term = ((uint32_t)(lane >> 4) * 8u + (uint32_t)(lane & 7)) * 48u
                          + (uint32_t)((lane >> 3) & 1) * 16u;
    const uint32_t bterm  = (uint32_t)(lane & 7) * 144u + (uint32_t)(lane >> 3) * 16u;

    // z split by feature parity: za[t]=feat 2t, zb[t]=feat 2t+1
    float za[8], zb[8];
    if (valid) {
        const float4* xr = (const float4*)(x + (size_t)row * 16);
        #pragma unroll
        for (int qq = 0; qq < 4; qq++) {
            float4 v = xr[qq];
            za[2 * qq] = v.x;     zb[2 * qq] = v.y;
            za[2 * qq + 1] = v.z; zb[2 * qq + 1] = v.w;
        }
    } else {
        #pragma unroll
        for (int t = 0; t < 8; t++) { za[t] = 0.0f; zb[t] = 0.0f; }
    }

    float logdet = 0.0f;

    #pragma unroll 1
    for (int l = 7; l >= 0; --l) {
        __syncthreads();   // all warps finished previous layer -> safe to restage

        // -------- stage small weights + W1T + B tiles into smem --------
        if (tid < 256) sW0[tid] = W0g[l * 256 + tid];
        if (tid < 64) sb1[tid] = b1g[l * 64 + tid];
        if (tid < 16) {
            sb0[tid] = b0g[l * 16 + tid];
            ssc[tid] = scaleg[l * 16 + tid];
            ssh[tid] = shiftg[l * 16 + tid];
        }
        if (tid < 256) sbf[tid] = g_bf[l * 256 + tid];
        if (tid >= 256 && tid < 320) {
            int i = tid - 256;     // W1T row i: 16 fp16 = 2 uint4
            const uint4* src = (const uint4*)(g_W1T + l * 1024 + i * 16);
            uint4* dst = (uint4*)(smem + SM_W1T + i * 48);
            dst[0] = src[0]; dst[1] = src[1];
        }
        if (tid < 256) {
            // B row tid (64 fp16 = 8 uint4)
            const uint4* src = (const uint4*)(g_Bh + l * 16384) + tid * 8;
            uint4* dst = (uint4*)(smem + SM_BH + tid * 144);
            #pragma unroll
            for (int c = 0; c < 8; c++) dst[c] = src[c];
        }
        __syncthreads();   // staging visible; warps free-run until next layer

        const int par = l & 1;

        // -------- stage 0: h0 = tanh(mz @ W0 + b0) (scalar, tiny) --------
        float h0[16];
        #pragma unroll
        for (int j = 0; j < 16; ++j) {
            float a = sb0[j];
            #pragma unroll
            for (int t = 0; t < 8; ++t) {
                float zk = par ? za[t] : zb[t];     // kept parity = 1-par
                int fk = 2 * t + 1 - par;
                a += zk * sW0[fk * 16 + j];
            }
            h0[j] = fast_tanh(a);
        }

        // -------- h0 -> warp-local bounce (fp16), then ldmatrix ------
        {
            uint32_t ph[8];
            #pragma unroll
            for (int i = 0; i < 8; ++i) ph[i] = pack_h2(h0[2 * i], h0[2 * i + 1]);
            char* hb = smem + SM_H0 + tid * 48;
            *(uint4*)(hb)      = make_uint4(ph[0], ph[1], ph[2], ph[3]);
            *(uint4*)(hb + 16) = make_uint4(ph[4], ph[5], ph[6], ph[7]);
        }
        __syncwarp();

        uint32_t Ha[2][4];
        {
            uint32_t rb = SM_H0 + (uint32_t)(32 * w) * 48u + h0term;
            ldm_x4(Ha[0][0], Ha[0][1], Ha[0][2], Ha[0][3], smb + rb);
            ldm_x4(Ha[1][0], Ha[1][1], Ha[1][2], Ha[1][3], smb + rb + 16 * 48);
        }

        // -------- W1T fragments --------
        uint32_t Wb[8][2];
        #pragma unroll
        for (int jj = 0; jj < 4; ++jj) {
            ldm_x4(Wb[2*jj][0], Wb[2*jj][1], Wb[2*jj+1][0], Wb[2*jj+1][1],
                   smb + SM_W1T + (uint32_t)(jj * 16 * 48) + w1term);
        }

        // bias pairs for this lane's columns
        float2 b1j[8];
        #pragma unroll
        for (int j = 0; j < 8; ++j) b1j[j] = *(float2*)(sb1 + 8 * j + 2 * q);

        // -------- stage 1 GEMM + tanh -> stage-2 A fragments in registers ----
        uint32_t Ah[2][4][4];
        #pragma unroll
        for (int m = 0; m < 2; ++m) {
            float d[8][4];
            #pragma unroll
            for (int j = 0; j < 8; ++j) {
                d[j][0] = b1j[j].x; d[j][1] = b1j[j].y;
                d[j][2] = b1j[j].x; d[j][3] = b1j[j].y;
            }
            #pragma unroll
            for (int j = 0; j < 8; ++j) {
                mma_f16(d[j][0], d[j][1], d[j][2], d[j][3],
                        Ha[m][0], Ha[m][1], Ha[m][2], Ha[m][3], Wb[j][0], Wb[j][1]);
            }
            // h1 = tanh(d); D-fragment == stage-2 A-fragment layout
            #pragma unroll
            for (int ks = 0; ks < 4; ++ks) {
                #pragma unroll
                for (int hh = 0; hh < 2; ++hh) {
                    int j = 2 * ks + hh;
                    float v0 = fast_tanh(d[j][0]);
                    float v1 = fast_tanh(d[j][1]);
                    float v2 = fast_tanh(d[j][2]);
                    float v3 = fast_tanh(d[j][3]);
                    Ah[m][ks][2 * hh]     = pack_h2(v0, v1);
                    Ah[m][ks][2 * hh + 1] = pack_h2(v2, v3);
                }
            }
        }

        float* pwarp = (float*)(smem + SM_PAR + w * 4352);   // [32][34], warp-local

        // -------- per transformed feature: stage-2 mma + spline --------
        #pragma unroll 1
        for (int t = 0; t < 8; ++t) {
            #pragma unroll
            for (int j = 0; j < 4; ++j) {
                uint32_t nb = (uint32_t)(t * 32 + 8 * j) * 144u + bterm;
                uint32_t Bh[4][2];
                ldm_x4(Bh[0][0], Bh[0][1], Bh[1][0], Bh[1][1], smb + SM_BH + nb);
                ldm_x4(Bh[2][0], Bh[2][1], Bh[3][0], Bh[3][1], smb + SM_BH + nb + 64u);

                #pragma unroll
                for (int m = 0; m < 2; ++m) {
                    // two independent half-chains (ks 0-1 / ks 2-3) -> ILP
                    float da0 = 0.0f, da1 = 0.0f, da2 = 0.0f, da3 = 0.0f;
                    float db0 = 0.0f, db1 = 0.0f, db2 = 0.0f, db3 = 0.0f;
                    mma_f16(da0, da1, da2, da3,
                            Ah[m][0][0], Ah[m][0][1], Ah[m][0][2], Ah[m][0][3],
                            Bh[0][0], Bh[0][1]);
                    mma_f16(db0, db1, db2, db3,
                            Ah[m][2][0], Ah[m][2][1], Ah[m][2][2], Ah[m][2][3],
                            Bh[2][0], Bh[2][1]);
                    mma_f16(da0, da1, da2, da3,
                            Ah[m][1][0], Ah[m][1][1], Ah[m][1][2], Ah[m][1][3],
                            Bh[1][0], Bh[1][1]);
                    mma_f16(db0, db1, db2, db3,
                            Ah[m][3][0], Ah[m][3][1], Ah[m][3][2], Ah[m][3][3],
                            Bh[3][0], Bh[3][1]);
                    float d0 = da0 + db0, d1 = da1 + db1;
                    float d2 = da2 + db2, d3 = da3 + db3;
                    int g = lane >> 2;
                    int r0 = 16 * m + g;
                    int c0 = 8 * j + 2 * q;
                    *(float2*)(pwarp + r0 * 34 + c0)       = make_float2(d0, d1);
                    *(float2*)(pwarp + (r0 + 8) * 34 + c0) = make_float2(d2, d3);
                }
            }
            __syncwarp();

            // gather this thread's row params + bias (float2)
            float acc[25];
            {
                const float2* pr = (const float2*)(pwarp + lane * 34);
                #pragma unroll
                for (int p = 0; p < 12; ++p) {
                    float2 v = pr[p];
                    acc[2 * p]     = v.x + sbf[t * 32 + 2 * p];
                    acc[2 * p + 1] = v.y + sbf[t * 32 + 2 * p + 1];
                }
                acc[24] = pwarp[lane * 34 + 24] + sbf[t * 32 + 24];
            }
            __syncwarp();   // params buffer free for next feature

            // ---- RQ spline forward + log-det ----
            float xv = par ? zb[t] : za[t];

            float mw = acc[0];
            #pragma unroll
            for (int k = 1; k < 8; ++k) mw = fmaxf(mw, acc[k]);
            float ew[8]; float swsum = 0.0f;
            #pragma unroll
            for (int k = 0; k < 8; ++k) { ew[k] = __expf(acc[k] - mw); swsum += ew[k]; }
            float cw = __fdividef(19.9992f, swsum);

            float mh = acc[8];
            #pragma unroll
            for (int k = 1; k < 8; ++k) mh = fmaxf(mh, acc[8 + k]);
            float eh[8]; float shsum = 0.0f;
            #pragma unroll
            for (int k = 0; k < 8; ++k) { eh[k] = __expf(acc[8 + k] - mh); shsum += eh[k]; }
            float chh = __fdividef(19.9992f, shsum);

            float cum = -10.0f, xk = -10.0f;
            int idx = 0;
            #pragma unroll
            for (int k = 0; k < 7; ++k) {
                cum += ew[k] * cw + 1e-4f;
                if (xv >= cum) { xk = cum; idx = k + 1; }
            }

            float yk = -10.0f, bh = 0.0f, bw = 1.0f, udk = 0.0f, udk1 = 0.0f;
            #pragma unroll
            for (int k = 0; k < 8; ++k) {
                float hh = eh[k] * chh + 1e-4f;
                if (k < idx) yk += hh;
                if (k == idx) {
                    bh = hh;
                    bw = ew[k] * cw + 1e-4f;
                    udk = acc[16 + k];
                    udk1 = acc[17 + k];
                }
            }

            float dk  = softplus_f(udk  + 0.54116665f) + 1e-4f;
            float dk1 = softplus_f(udk1 + 0.54116665f) + 1e-4f;
            float s   = __fdividef(bh, bw);
            float zt  = __saturatef(__fdividef(xv - xk, bw));
            float z1  = 1.0f - zt;
            float zz  = zt * zt;
            float zz1 = zt * z1;
            float den = s + (dk1 + dk - 2.0f * s) * zz1;
            float y   = yk + bh * __fdividef(s * zz + dk * zz1, den);
            float numld = dk1 * zz + 2.0f * s * zz1 + dk * z1 * z1;
            float ld = 2.0f * __logf(s) + __logf(numld) - 2.0f * __logf(den);

            bool outside = (xv <= -10.0f) || (xv >= 10.0f);
            if (outside) { y = xv; ld = 0.0f; }

            if (par) zb[t] = y; else za[t] = y;
            logdet += ld;
        }

        // -------- affine: z = z*scale + shift --------
        #pragma unroll
        for (int t = 0; t < 8; ++t) {
            za[t] = za[t] * ssc[2 * t]     + ssh[2 * t];
            zb[t] = zb[t] * ssc[2 * t + 1] + ssh[2 * t + 1];
        }
        logdet += g_lc[l];
    }

    float ss = 0.0f;
    #pragma unroll
    for (int t = 0; t < 8; ++t) ss += za[t] * za[t] + zb[t] * zb[t];

    if (valid) out[row] = -0.5f * ss - 14.703170f + logdet;   // 8*log(2*pi)
}

extern "C" void kernel_launch(void* const* d_in, const int* in_sizes, int n_in,
                              void* d_out, int out_size) {
    const float* x     = (const float*)d_in[0];
    const float* W0    = (const float*)d_in[1];
    const float* b0    = (const float*)d_in[2];
    const float* W1    = (const float*)d_in[3];
    const float* b1    = (const float*)d_in[4];
    const float* W2    = (const float*)d_in[5];
    const float* b2    = (const float*)d_in[6];
    const float* Wout  = (const float*)d_in[7];
    const float* bout  = (const float*)d_in[8];
    const float* scale = (const float*)d_in[9];
    const float* shift = (const float*)d_in[10];

    int B = in_sizes[0] / 16;

    const int NP = 8 * 256 * 64 + 8 * 256 + 8 + 8 * 64 * 16;
    precompute_kernel<<<(NP + 255) / 256, 256>>>(W1, W2, b2, Wout, bout, scale);

    cudaFuncSetAttribute(flow_kernel, cudaFuncAttributeMaxDynamicSharedMemorySize, SM_TOTAL);
    flow_kernel<<<(B + BLK - 1) / BLK, BLK, SM_TOTAL>>>(
        x, W0, b0, b1, scale, shift, (float*)d_out, B);
}

// round 16
// speedup vs baseline: 3.0184x; 1.1969x over previous
#include <cuda_runtime.h>
#include <cuda_bf16.h>
#include <cuda_fp16.h>
#include <cstdint>

// ---------------------------------------------------------------------------
// RQ-spline coupling flow log-prob, fused. Stage-1 AND stage-2 GEMMs on tensor
// cores via mma.sync m16n8k16 fp16 single-pass.
// F=16, H1=H2=64, K=8, L=8, NBP=25.
//
// R15 -> R16: BLK 512->448 (grid 293 = two nearly-full waves vs 1.73),
// tanh.approx.f32 for h0/h1 (kills the exp+div tanh blocks),
// bias-init stage-2 accumulators (-13 LDS/-13 FADD per t),
// single-log log-det with reciprocal reuse (-2 MUFU logs, -1 div per t).
// ---------------------------------------------------------------------------

#define BLK 448          // threads per CTA = rows per CTA (14 warps)

// B operand Wf^T, [l][n=256][k=64] fp16
__device__ __align__(16) unsigned short g_Bh[8 * 256 * 64];
// W1^T, [l][n=64][k=16] fp16
__device__ __align__(16) unsigned short g_W1T[8 * 64 * 16];
__device__ __align__(16) float g_bf[8 * 256];    // bias, padded t*32+p layout
__device__ float g_lc[8];

// ---------------- precompute ----------------
__global__ void precompute_kernel(const float* __restrict__ W1,
                                  const float* __restrict__ W2,
                                  const float* __restrict__ b2,
                                  const float* __restrict__ Wout,
                                  const float* __restrict__ bout,
                                  const float* __restrict__ scale) {
    const int NWF = 8 * 256 * 64;
    const int NBF = 8 * 256;
    const int NW1 = 8 * 64 * 16;
    int idx = blockIdx.x * blockDim.x + threadIdx.x;
    if (idx < NWF) {
        int l = idx / 16384;
        int r = idx % 16384;
        int n = r / 64;             // padded output col: t*32 + p
        int k = r % 64;             // h1 index
        int t = n >> 5, p = n & 31;
        float v = 0.0f;
        if (p < 25) {
            int col = (2 * t + (l & 1)) * 25 + p;   // transformed feature 2t+(l&1)
            const float* w2row = W2 + l * 4096 + k * 64;
            const float* wo = Wout + l * 25600 + col;
            #pragma unroll 8
            for (int j = 0; j < 64; j++) v += w2row[j] * wo[j * 400];
        }
        g_Bh[idx] = __half_as_ushort(__float2half_rn(v));
    } else if (idx < NWF + NBF) {
        int e = idx - NWF;
        int l = e / 256;
        int n = e % 256;
        int t = n >> 5, p = n & 31;
        float v = 0.0f;
        if (p < 25) {
            int col = (2 * t + (l & 1)) * 25 + p;
            const float* b2r = b2 + l * 64;
            const float* wo = Wout + l * 25600 + col;
            #pragma unroll 8
            for (int j = 0; j < 64; j++) v += b2r[j] * wo[j * 400];
            v += bout[l * 400 + col];
        }
        g_bf[e] = v;
    } else if (idx < NWF + NBF + 8) {
        int l = idx - NWF - NBF;
        float v = 0.0f;
        for (int f = 0; f < 16; f++) v += logf(fabsf(scale[l * 16 + f]));
        g_lc[l] = v;
    } else if (idx < NWF + NBF + 8 + NW1) {
        int e = idx - NWF - NBF - 8;
        int l = e / 1024;
        int r = e % 1024;
        int n = r / 16;             // h1 col
        int k = r % 16;             // h0 index
        float v = W1[l * 1024 + k * 64 + n];
        g_W1T[e] = __half_as_ushort(__float2half_rn(v));
    }
}

__device__ __forceinline__ float tanh_fast(float x) {
    float y;
    asm("tanh.approx.f32 %0, %1;" : "=f"(y) : "f"(x));
    return y;
}
__device__ __forceinline__ float softplus_f(float t) {
    float r = __logf(1.0f + __expf(t));
    return (t > 20.0f) ? t : r;
}
__device__ __forceinline__ uint32_t pack_h2(float v0, float v1) {
    __half2 h = __floats2half2_rn(v0, v1);
    return *reinterpret_cast<uint32_t*>(&h);
}

__device__ __forceinline__ void mma_f16(float& d0, float& d1, float& d2, float& d3,
                                        uint32_t a0, uint32_t a1, uint32_t a2, uint32_t a3,
                                        uint32_t b0, uint32_t b1) {
    asm volatile(
        "mma.sync.aligned.m16n8k16.row.col.f32.f16.f16.f32 "
        "{%0,%1,%2,%3}, {%4,%5,%6,%7}, {%8,%9}, {%0,%1,%2,%3};"
        : "+f"(d0), "+f"(d1), "+f"(d2), "+f"(d3)
        : "r"(a0), "r"(a1), "r"(a2), "r"(a3), "r"(b0), "r"(b1));
}

__device__ __forceinline__ void ldm_x4(uint32_t& r0, uint32_t& r1,
                                       uint32_t& r2, uint32_t& r3, uint32_t saddr) {
    asm volatile("ldmatrix.sync.aligned.m8n8.x4.shared.b16 {%0,%1,%2,%3}, [%4];"
                 : "=r"(r0), "=r"(r1), "=r"(r2), "=r"(r3) : "r"(saddr));
}

// ---------------- smem layout (bytes) ----------------
static constexpr int SM_W     = 0;                      // small weights (2560 B)
static constexpr int SM_H0    = 2560;                   // BLK rows x 48 B (32B data)
static constexpr int SM_W1T   = SM_H0 + BLK * 48;       // 64 x 48 B = 3072
static constexpr int SM_BH    = SM_W1T + 3072;          // 256 n x 144 B (128B data)
static constexpr int SM_PAR   = SM_BH + 256 * 144;      // 14 warps x 4352 B
static constexpr int SM_TOTAL = SM_PAR + (BLK / 32) * 4352;   // = 124928 B

__global__ __launch_bounds__(BLK, 1)
void flow_kernel(const float* __restrict__ x,
                 const float* __restrict__ W0g, const float* __restrict__ b0g,
                 const float* __restrict__ b1g,
                 const float* __restrict__ scaleg, const float* __restrict__ shiftg,
                 float* __restrict__ out, int B) {
    extern __shared__ __align__(16) char smem[];
    const uint32_t smb = (uint32_t)__cvta_generic_to_shared(smem);

    float* sW0 = (float*)(smem + SM_W);   // 256
    float* sb0 = sW0 + 256;               // 16
    float* sb1 = sb0 + 16;                // 64
    float* ssc = sb1 + 64;                // 16
    float* ssh = ssc + 16;                // 16
    float* sbf = ssh + 16;                // 256

    const int tid  = threadIdx.x;
    const int w    = tid >> 5;            // warp id (0..13)
    const int lane = tid & 31;
    const int q    = lane & 3;
    const int row  = blockIdx.x * BLK + tid;
    const bool valid = row < B;

    // ldmatrix lane terms
    const uint32_t h0term = (uint32_t)(lane & 15) * 48u + (uint32_t)(lane >> 4) * 16u;
    const uint32_t w1term = ((uint32_t)(lane >> 4) * 8u + (uint32_t)(lane & 7)) * 48u
                          + (uint32_t)((lane >> 3) & 1) * 16u;
    const uint32_t bterm  = (uint32_t)(lane & 7) * 144u + (uint32_t)(lane >> 3) * 16u;

    // z split by feature parity: za[t]=feat 2t, zb[t]=feat 2t+1
    float za[8], zb[8];
    if (valid) {
        const float4* xr = (const float4*)(x + (size_t)row * 16);
        #pragma unroll
        for (int qq = 0; qq < 4; qq++) {
            float4 v = xr[qq];
            za[2 * qq] = v.x;     zb[2 * qq] = v.y;
            za[2 * qq + 1] = v.z; zb[2 * qq + 1] = v.w;
        }
    } else {
        #pragma unroll
        for (int t = 0; t < 8; t++) { za[t] = 0.0f; zb[t] = 0.0f; }
    }

    float logdet = 0.0f;

    #pragma unroll 1
    for (int l = 7; l >= 0; --l) {
        __syncthreads();   // all warps finished previous layer -> safe to restage

        // -------- stage small weights + W1T + B tiles into smem --------
        if (tid < 256) sW0[tid] = W0g[l * 256 + tid];
        if (tid < 64) sb1[tid] = b1g[l * 64 + tid];
        if (tid < 16) {
            sb0[tid] = b0g[l * 16 + tid];
            ssc[tid] = scaleg[l * 16 + tid];
            ssh[tid] = shiftg[l * 16 + tid];
        }
        if (tid < 256) sbf[tid] = g_bf[l * 256 + tid];
        if (tid >= 256 && tid < 320) {
            int i = tid - 256;     // W1T row i: 16 fp16 = 2 uint4
            const uint4* src = (const uint4*)(g_W1T + l * 1024 + i * 16);
            uint4* dst = (uint4*)(smem + SM_W1T + i * 48);
            dst[0] = src[0]; dst[1] = src[1];
        }
        if (tid < 256) {
            // B row tid (64 fp16 = 8 uint4)
            const uint4* src = (const uint4*)(g_Bh + l * 16384) + tid * 8;
            uint4* dst = (uint4*)(smem + SM_BH + tid * 144);
            #pragma unroll
            for (int c = 0; c < 8; c++) dst[c] = src[c];
        }
        __syncthreads();   // staging visible; warps free-run until next layer

        const int par = l & 1;

        // -------- stage 0: h0 = tanh(mz @ W0 + b0) (scalar, tiny) --------
        float h0[16];
        #pragma unroll
        for (int j = 0; j < 16; ++j) {
            float a = sb0[j];
            #pragma unroll
            for (int t = 0; t < 8; ++t) {
                float zk = par ? za[t] : zb[t];     // kept parity = 1-par
                int fk = 2 * t + 1 - par;
                a += zk * sW0[fk * 16 + j];
            }
            h0[j] = tanh_fast(a);
        }

        // -------- h0 -> warp-local bounce (fp16), then ldmatrix ------
        {
            uint32_t ph[8];
            #pragma unroll
            for (int i = 0; i < 8; ++i) ph[i] = pack_h2(h0[2 * i], h0[2 * i + 1]);
            char* hb = smem + SM_H0 + tid * 48;
            *(uint4*)(hb)      = make_uint4(ph[0], ph[1], ph[2], ph[3]);
            *(uint4*)(hb + 16) = make_uint4(ph[4], ph[5], ph[6], ph[7]);
        }
        __syncwarp();

        uint32_t Ha[2][4];
        {
            uint32_t rb = SM_H0 + (uint32_t)(32 * w) * 48u + h0term;
            ldm_x4(Ha[0][0], Ha[0][1], Ha[0][2], Ha[0][3], smb + rb);
            ldm_x4(Ha[1][0], Ha[1][1], Ha[1][2], Ha[1][3], smb + rb + 16 * 48);
        }

        // -------- W1T fragments --------
        uint32_t Wb[8][2];
        #pragma unroll
        for (int jj = 0; jj < 4; ++jj) {
            ldm_x4(Wb[2*jj][0], Wb[2*jj][1], Wb[2*jj+1][0], Wb[2*jj+1][1],
                   smb + SM_W1T + (uint32_t)(jj * 16 * 48) + w1term);
        }

        // bias pairs for this lane's columns
        float2 b1j[8];
        #pragma unroll
        for (int j = 0; j < 8; ++j) b1j[j] = *(float2*)(sb1 + 8 * j + 2 * q);

        // -------- stage 1 GEMM + tanh -> stage-2 A fragments in registers ----
        uint32_t Ah[2][4][4];
        #pragma unroll
        for (int m = 0; m < 2; ++m) {
            float d[8][4];
            #pragma unroll
            for (int j = 0; j < 8; ++j) {
                d[j][0] = b1j[j].x; d[j][1] = b1j[j].y;
                d[j][2] = b1j[j].x; d[j][3] = b1j[j].y;
            }
            #pragma unroll
            for (int j = 0; j < 8; ++j) {
                mma_f16(d[j][0], d[j][1], d[j][2], d[j][3],
                        Ha[m][0], Ha[m][1], Ha[m][2], Ha[m][3], Wb[j][0], Wb[j][1]);
            }
            // h1 = tanh(d); D-fragment == stage-2 A-fragment layout
            #pragma unroll
            for (int ks = 0; ks < 4; ++ks) {
                #pragma unroll
                for (int hh = 0; hh < 2; ++hh) {
                    int j = 2 * ks + hh;
                    float v0 = tanh_fast(d[j][0]);
                    float v1 = tanh_fast(d[j][1]);
                    float v2 = tanh_fast(d[j][2]);
                    float v3 = tanh_fast(d[j][3]);
                    Ah[m][ks][2 * hh]     = pack_h2(v0, v1);
                    Ah[m][ks][2 * hh + 1] = pack_h2(v2, v3);
                }
            }
        }

        float* pwarp = (float*)(smem + SM_PAR + w * 4352);   // [32][34], warp-local

        // -------- per transformed feature: stage-2 mma + spline --------
        #pragma unroll 1
        for (int t = 0; t < 8; ++t) {
            #pragma unroll
            for (int j = 0; j < 4; ++j) {
                uint32_t nb = (uint32_t)(t * 32 + 8 * j) * 144u + bterm;
                uint32_t Bh[4][2];
                ldm_x4(Bh[0][0], Bh[0][1], Bh[1][0], Bh[1][1], smb + SM_BH + nb);
                ldm_x4(Bh[2][0], Bh[2][1], Bh[3][0], Bh[3][1], smb + SM_BH + nb + 64u);

                // bias for this lane's two columns (col-dependent only)
                float2 bb = *(float2*)(sbf + t * 32 + 8 * j + 2 * q);

                #pragma unroll
                for (int m = 0; m < 2; ++m) {
                    // two independent half-chains; da seeded with the bias
                    float da0 = bb.x, da1 = bb.y, da2 = bb.x, da3 = bb.y;
                    float db0 = 0.0f, db1 = 0.0f, db2 = 0.0f, db3 = 0.0f;
                    mma_f16(da0, da1, da2, da3,
                            Ah[m][0][0], Ah[m][0][1], Ah[m][0][2], Ah[m][0][3],
                            Bh[0][0], Bh[0][1]);
                    mma_f16(db0, db1, db2, db3,
                            Ah[m][2][0], Ah[m][2][1], Ah[m][2][2], Ah[m][2][3],
                            Bh[2][0], Bh[2][1]);
                    mma_f16(da0, da1, da2, da3,
                            Ah[m][1][0], Ah[m][1][1], Ah[m][1][2], Ah[m][1][3],
                            Bh[1][0], Bh[1][1]);
                    mma_f16(db0, db1, db2, db3,
                            Ah[m][3][0], Ah[m][3][1], Ah[m][3][2], Ah[m][3][3],
                            Bh[3][0], Bh[3][1]);
                    float d0 = da0 + db0, d1 = da1 + db1;
                    float d2 = da2 + db2, d3 = da3 + db3;
                    int g = lane >> 2;
                    int r0 = 16 * m + g;
                    int c0 = 8 * j + 2 * q;
                    *(float2*)(pwarp + r0 * 34 + c0)       = make_float2(d0, d1);
                    *(float2*)(pwarp + (r0 + 8) * 34 + c0) = make_float2(d2, d3);
                }
            }
            __syncwarp();

            // gather this thread's row params (bias already folded in)
            float acc[25];
            {
                const float2* pr = (const float2*)(pwarp + lane * 34);
                #pragma unroll
                for (int p = 0; p < 12; ++p) {
                    float2 v = pr[p];
                    acc[2 * p]     = v.x;
                    acc[2 * p + 1] = v.y;
                }
                acc[24] = pwarp[lane * 34 + 24];
            }
            __syncwarp();   // params buffer free for next feature

            // ---- RQ spline forward + log-det ----
            float xv = par ? zb[t] : za[t];

            float mw = acc[0];
            #pragma unroll
            for (int k = 1; k < 8; ++k) mw = fmaxf(mw, acc[k]);
            float ew[8]; float swsum = 0.0f;
            #pragma unroll
            for (int k = 0; k < 8; ++k) { ew[k] = __expf(acc[k] - mw); swsum += ew[k]; }
            float cw = __fdividef(19.9992f, swsum);

            float mh = acc[8];
            #pragma unroll
            for (int k = 1; k < 8; ++k) mh = fmaxf(mh, acc[8 + k]);
            float eh[8]; float shsum = 0.0f;
            #pragma unroll
            for (int k = 0; k < 8; ++k) { eh[k] = __expf(acc[8 + k] - mh); shsum += eh[k]; }
            float chh = __fdividef(19.9992f, shsum);

            float cum = -10.0f, xk = -10.0f;
            int idx = 0;
            #pragma unroll
            for (int k = 0; k < 7; ++k) {
                cum += ew[k] * cw + 1e-4f;
                if (xv >= cum) { xk = cum; idx = k + 1; }
            }

            float yk = -10.0f, bh = 0.0f, bw = 1.0f, udk = 0.0f, udk1 = 0.0f;
            #pragma unroll
            for (int k = 0; k < 8; ++k) {
                float hh = eh[k] * chh + 1e-4f;
                if (k < idx) yk += hh;
                if (k == idx) {
                    bh = hh;
                    bw = ew[k] * cw + 1e-4f;
                    udk = acc[16 + k];
                    udk1 = acc[17 + k];
                }
            }

            float dk  = softplus_f(udk  + 0.54116665f) + 1e-4f;
            float dk1 = softplus_f(udk1 + 0.54116665f) + 1e-4f;
            float s   = __fdividef(bh, bw);
            float zt  = __saturatef(__fdividef(xv - xk, bw));
            float z1  = 1.0f - zt;
            float zz  = zt * zt;
            float zz1 = zt * z1;
            float den = s + (dk1 + dk - 2.0f * s) * zz1;
            float rden = __fdividef(1.0f, den);
            float y   = yk + bh * (s * zz + dk * zz1) * rden;
            float numld = dk1 * zz + 2.0f * s * zz1 + dk * z1 * z1;
            // ld = 2log(s) + log(numld) - 2log(den), folded to one log
            float ld = __logf(s * s * numld * rden * rden);

            bool outside = (xv <= -10.0f) || (xv >= 10.0f);
            if (outside) { y = xv; ld = 0.0f; }

            if (par) zb[t] = y; else za[t] = y;
            logdet += ld;
        }

        // -------- affine: z = z*scale + shift --------
        #pragma unroll
        for (int t = 0; t < 8; ++t) {
            za[t] = za[t] * ssc[2 * t]     + ssh[2 * t];
            zb[t] = zb[t] * ssc[2 * t + 1] + ssh[2 * t + 1];
        }
        logdet += g_lc[l];
    }

    float ss = 0.0f;
    #pragma unroll
    for (int t = 0; t < 8; ++t) ss += za[t] * za[t] + zb[t] * zb[t];

    if (valid) out[row] = -0.5f * ss - 14.703170f + logdet;   // 8*log(2*pi)
}

extern "C" void kernel_launch(void* const* d_in, const int* in_sizes, int n_in,
                              void* d_out, int out_size) {
    const float* x     = (const float*)d_in[0];
    const float* W0    = (const float*)d_in[1];
    const float* b0    = (const float*)d_in[2];
    const float* W1    = (const float*)d_in[3];
    const float* b1    = (const float*)d_in[4];
    const float* W2    = (const float*)d_in[5];
    const float* b2    = (const float*)d_in[6];
    const float* Wout  = (const float*)d_in[7];
    const float* bout  = (const float*)d_in[8];
    const float* scale = (const float*)d_in[9];
    const float* shift = (const float*)d_in[10];

    int B = in_sizes[0] / 16;

    const int NP = 8 * 256 * 64 + 8 * 256 + 8 + 8 * 64 * 16;
    precompute_kernel<<<(NP + 255) / 256, 256>>>(W1, W2, b2, Wout, bout, scale);

    cudaFuncSetAttribute(flow_kernel, cudaFuncAttributeMaxDynamicSharedMemorySize, SM_TOTAL);
    flow_kernel<<<(B + BLK - 1) / BLK, BLK, SM_TOTAL>>>(
        x, W0, b0, b1, scale, shift, (float*)d_out, B);
}

// round 17
// speedup vs baseline: 3.3693x; 1.1163x over previous
#include <cuda_runtime.h>
#include <cuda_bf16.h>
#include <cuda_fp16.h>
#include <cstdint>

// ---------------------------------------------------------------------------
// RQ-spline coupling flow log-prob, fused. Stage-1 AND stage-2 GEMMs on tensor
// cores via mma.sync m16n8k16 fp16 single-pass.
// F=16, H1=H2=64, K=8, L=8, NBP=25.
//
// R16 -> R17 (L1=80% is the binding pipe -> LSU instruction diet):
//  * stage-0 restructured t-outer/j-inner -> LDS.128 W0 loads (144 -> 36)
//  * cp.async staging for B / W1T / small weights (LDG+STS pair -> 1 instr)
//  * PAR D-bounce packed fp16 (gather 13 LDS.64 -> 6 LDS.64 + 1 LDS.32),
//    stride-20-uint32 rows: conflict-free scatter, <=2-way gather
// ---------------------------------------------------------------------------

#define BLK 448          // threads per CTA = rows per CTA (14 warps)

// B operand Wf^T, [l][n=256][k=64] fp16
__device__ __align__(16) unsigned short g_Bh[8 * 256 * 64];
// W1^T, [l][n=64][k=16] fp16
__device__ __align__(16) unsigned short g_W1T[8 * 64 * 16];
__device__ __align__(16) float g_bf[8 * 256];    // bias, padded t*32+p layout
__device__ float g_lc[8];

// ---------------- precompute ----------------
__global__ void precompute_kernel(const float* __restrict__ W1,
                                  const float* __restrict__ W2,
                                  const float* __restrict__ b2,
                                  const float* __restrict__ Wout,
                                  const float* __restrict__ bout,
                                  const float* __restrict__ scale) {
    const int NWF = 8 * 256 * 64;
    const int NBF = 8 * 256;
    const int NW1 = 8 * 64 * 16;
    int idx = blockIdx.x * blockDim.x + threadIdx.x;
    if (idx < NWF) {
        int l = idx / 16384;
        int r = idx % 16384;
        int n = r / 64;             // padded output col: t*32 + p
        int k = r % 64;             // h1 index
        int t = n >> 5, p = n & 31;
        float v = 0.0f;
        if (p < 25) {
            int col = (2 * t + (l & 1)) * 25 + p;   // transformed feature 2t+(l&1)
            const float* w2row = W2 + l * 4096 + k * 64;
            const float* wo = Wout + l * 25600 + col;
            #pragma unroll 8
            for (int j = 0; j < 64; j++) v += w2row[j] * wo[j * 400];
        }
        g_Bh[idx] = __half_as_ushort(__float2half_rn(v));
    } else if (idx < NWF + NBF) {
        int e = idx - NWF;
        int l = e / 256;
        int n = e % 256;
        int t = n >> 5, p = n & 31;
        float v = 0.0f;
        if (p < 25) {
            int col = (2 * t + (l & 1)) * 25 + p;
            const float* b2r = b2 + l * 64;
            const float* wo = Wout + l * 25600 + col;
            #pragma unroll 8
            for (int j = 0; j < 64; j++) v += b2r[j] * wo[j * 400];
            v += bout[l * 400 + col];
        }
        g_bf[e] = v;
    } else if (idx < NWF + NBF + 8) {
        int l = idx - NWF - NBF;
        float v = 0.0f;
        for (int f = 0; f < 16; f++) v += logf(fabsf(scale[l * 16 + f]));
        g_lc[l] = v;
    } else if (idx < NWF + NBF + 8 + NW1) {
        int e = idx - NWF - NBF - 8;
        int l = e / 1024;
        int r = e % 1024;
        int n = r / 16;             // h1 col
        int k = r % 16;             // h0 index
        float v = W1[l * 1024 + k * 64 + n];
        g_W1T[e] = __half_as_ushort(__float2half_rn(v));
    }
}

__device__ __forceinline__ float tanh_fast(float x) {
    float y;
    asm("tanh.approx.f32 %0, %1;" : "=f"(y) : "f"(x));
    return y;
}
__device__ __forceinline__ float softplus_f(float t) {
    float r = __logf(1.0f + __expf(t));
    return (t > 20.0f) ? t : r;
}
__device__ __forceinline__ uint32_t pack_h2(float v0, float v1) {
    __half2 h = __floats2half2_rn(v0, v1);
    return *reinterpret_cast<uint32_t*>(&h);
}
__device__ __forceinline__ void cpa16(uint32_t smem_dst, const void* gsrc) {
    asm volatile("cp.async.ca.shared.global [%0], [%1], 16;"
                 :: "r"(smem_dst), "l"(gsrc) : "memory");
}

__device__ __forceinline__ void mma_f16(float& d0, float& d1, float& d2, float& d3,
                                        uint32_t a0, uint32_t a1, uint32_t a2, uint32_t a3,
                                        uint32_t b0, uint32_t b1) {
    asm volatile(
        "mma.sync.aligned.m16n8k16.row.col.f32.f16.f16.f32 "
        "{%0,%1,%2,%3}, {%4,%5,%6,%7}, {%8,%9}, {%0,%1,%2,%3};"
        : "+f"(d0), "+f"(d1), "+f"(d2), "+f"(d3)
        : "r"(a0), "r"(a1), "r"(a2), "r"(a3), "r"(b0), "r"(b1));
}

__device__ __forceinline__ void ldm_x4(uint32_t& r0, uint32_t& r1,
                                       uint32_t& r2, uint32_t& r3, uint32_t saddr) {
    asm volatile("ldmatrix.sync.aligned.m8n8.x4.shared.b16 {%0,%1,%2,%3}, [%4];"
                 : "=r"(r0), "=r"(r1), "=r"(r2), "=r"(r3) : "r"(saddr));
}

// ---------------- smem layout (bytes) ----------------
// small-weight block (float offsets): sW0@0(256) sb0@256(16) sb1@272(64)
// ssc@336(16) ssh@352(16) sbf@368(256)  -> 2496 B, all 16B-aligned
static constexpr int SM_W     = 0;                      // 2560 B
static constexpr int SM_H0    = 2560;                   // BLK rows x 48 B
static constexpr int SM_W1T   = SM_H0 + BLK * 48;       // 64 x 48 B = 3072
static constexpr int SM_BH    = SM_W1T + 3072;          // 256 n x 144 B
static constexpr int SM_PAR   = SM_BH + 256 * 144;      // 14 warps x 2560 B (fp16 pairs)
static constexpr int SM_TOTAL = SM_PAR + (BLK / 32) * 2560;   // = 99840 B

__global__ __launch_bounds__(BLK, 1)
void flow_kernel(const float* __restrict__ x,
                 const float* __restrict__ W0g, const float* __restrict__ b0g,
                 const float* __restrict__ b1g,
                 const float* __restrict__ scaleg, const float* __restrict__ shiftg,
                 float* __restrict__ out, int B) {
    extern __shared__ __align__(16) char smem[];
    const uint32_t smb = (uint32_t)__cvta_generic_to_shared(smem);

    float* sW0 = (float*)(smem + SM_W);   // 256
    float* sb0 = sW0 + 256;               // 16
    float* sb1 = sb0 + 16;                // 64
    float* ssc = sb1 + 64;                // 16
    float* ssh = ssc + 16;                // 16
    float* sbf = ssh + 16;                // 256

    const int tid  = threadIdx.x;
    const int w    = tid >> 5;            // warp id (0..13)
    const int lane = tid & 31;
    const int q    = lane & 3;
    const int g    = lane >> 2;
    const int row  = blockIdx.x * BLK + tid;
    const bool valid = row < B;

    // ldmatrix lane terms
    const uint32_t h0term = (uint32_t)(lane & 15) * 48u + (uint32_t)(lane >> 4) * 16u;
    const uint32_t w1term = ((uint32_t)(lane >> 4) * 8u + (uint32_t)(lane & 7)) * 48u
                          + (uint32_t)((lane >> 3) & 1) * 16u;
    const uint32_t bterm  = (uint32_t)(lane & 7) * 144u + (uint32_t)(lane >> 3) * 16u;

    // z split by feature parity: za[t]=feat 2t, zb[t]=feat 2t+1
    float za[8], zb[8];
    if (valid) {
        const float4* xr = (const float4*)(x + (size_t)row * 16);
        #pragma unroll
        for (int qq = 0; qq < 4; qq++) {
            float4 v = xr[qq];
            za[2 * qq] = v.x;     zb[2 * qq] = v.y;
            za[2 * qq + 1] = v.z; zb[2 * qq + 1] = v.w;
        }
    } else {
        #pragma unroll
        for (int t = 0; t < 8; t++) { za[t] = 0.0f; zb[t] = 0.0f; }
    }

    float logdet = 0.0f;

    #pragma unroll 1
    for (int l = 7; l >= 0; --l) {
        __syncthreads();   // all warps finished previous layer -> safe to restage

        // -------- cp.async staging of all per-layer tiles --------
        if (tid < 256) {
            // B row tid: 128 B
            uint32_t dst = smb + SM_BH + (uint32_t)tid * 144u;
            const char* src = (const char*)(g_Bh + l * 16384) + tid * 128;
            #pragma unroll
            for (int c = 0; c < 8; c++) cpa16(dst + c * 16, src + c * 16);
        }
        if (tid < 64) {
            cpa16(smb + (uint32_t)(SM_W) + tid * 16u, (const char*)(W0g + l * 256) + tid * 16);
        } else if (tid < 128) {
            int i = tid - 64;
            cpa16(smb + (uint32_t)(SM_W + 368 * 4) + i * 16u, (const char*)(g_bf + l * 256) + i * 16);
        } else if (tid < 144) {
            int i = tid - 128;
            cpa16(smb + (uint32_t)(SM_W + 272 * 4) + i * 16u, (const char*)(b1g + l * 64) + i * 16);
        } else if (tid < 148) {
            int i = tid - 144;
            cpa16(smb + (uint32_t)(SM_W + 256 * 4) + i * 16u, (const char*)(b0g + l * 16) + i * 16);
        } else if (tid < 152) {
            int i = tid - 148;
            cpa16(smb + (uint32_t)(SM_W + 336 * 4) + i * 16u, (const char*)(scaleg + l * 16) + i * 16);
        } else if (tid < 156) {
            int i = tid - 152;
            cpa16(smb + (uint32_t)(SM_W + 352 * 4) + i * 16u, (const char*)(shiftg + l * 16) + i * 16);
        } else if (tid >= 256 && tid < 320) {
            int i = tid - 256;     // W1T row i: 32 B
            uint32_t dst = smb + (uint32_t)SM_W1T + (uint32_t)i * 48u;
            const char* src = (const char*)(g_W1T + l * 1024 + i * 16);
            cpa16(dst, src);
            cpa16(dst + 16, src + 16);
        }
        asm volatile("cp.async.commit_group;" ::: "memory");
        asm volatile("cp.async.wait_group 0;" ::: "memory");
        __syncthreads();   // staging visible; warps free-run until next layer

        const int par = l & 1;

        // -------- stage 0: h0 = tanh(mz @ W0 + b0), vectorized LDS.128 ------
        float h0[16];
        {
            #pragma unroll
            for (int c = 0; c < 4; ++c) {
                float4 b = ((const float4*)sb0)[c];
                h0[4 * c + 0] = b.x; h0[4 * c + 1] = b.y;
                h0[4 * c + 2] = b.z; h0[4 * c + 3] = b.w;
            }
            #pragma unroll
            for (int t = 0; t < 8; ++t) {
                float zk = par ? za[t] : zb[t];     // kept parity = 1-par
                const float4* wr = (const float4*)(sW0 + (2 * t + 1 - par) * 16);
                #pragma unroll
                for (int c = 0; c < 4; ++c) {
                    float4 wv = wr[c];
                    h0[4 * c + 0] += zk * wv.x;
                    h0[4 * c + 1] += zk * wv.y;
                    h0[4 * c + 2] += zk * wv.z;
                    h0[4 * c + 3] += zk * wv.w;
                }
            }
            #pragma unroll
            for (int j = 0; j < 16; ++j) h0[j] = tanh_fast(h0[j]);
        }

        // -------- h0 -> warp-local bounce (fp16), then ldmatrix ------
        {
            uint32_t ph[8];
            #pragma unroll
            for (int i = 0; i < 8; ++i) ph[i] = pack_h2(h0[2 * i], h0[2 * i + 1]);
            char* hb = smem + SM_H0 + tid * 48;
            *(uint4*)(hb)      = make_uint4(ph[0], ph[1], ph[2], ph[3]);
            *(uint4*)(hb + 16) = make_uint4(ph[4], ph[5], ph[6], ph[7]);
        }
        __syncwarp();

        uint32_t Ha[2][4];
        {
            uint32_t rb = SM_H0 + (uint32_t)(32 * w) * 48u + h0term;
            ldm_x4(Ha[0][0], Ha[0][1], Ha[0][2], Ha[0][3], smb + rb);
            ldm_x4(Ha[1][0], Ha[1][1], Ha[1][2], Ha[1][3], smb + rb + 16 * 48);
        }

        // -------- W1T fragments --------
        uint32_t Wb[8][2];
        #pragma unroll
        for (int jj = 0; jj < 4; ++jj) {
            ldm_x4(Wb[2*jj][0], Wb[2*jj][1], Wb[2*jj+1][0], Wb[2*jj+1][1],
                   smb + SM_W1T + (uint32_t)(jj * 16 * 48) + w1term);
        }

        // bias pairs for this lane's columns
        float2 b1j[8];
        #pragma unroll
        for (int j = 0; j < 8; ++j) b1j[j] = *(float2*)(sb1 + 8 * j + 2 * q);

        // -------- stage 1 GEMM + tanh -> stage-2 A fragments in registers ----
        uint32_t Ah[2][4][4];
        #pragma unroll
        for (int m = 0; m < 2; ++m) {
            float d[8][4];
            #pragma unroll
            for (int j = 0; j < 8; ++j) {
                d[j][0] = b1j[j].x; d[j][1] = b1j[j].y;
                d[j][2] = b1j[j].x; d[j][3] = b1j[j].y;
            }
            #pragma unroll
            for (int j = 0; j < 8; ++j) {
                mma_f16(d[j][0], d[j][1], d[j][2], d[j][3],
                        Ha[m][0], Ha[m][1], Ha[m][2], Ha[m][3], Wb[j][0], Wb[j][1]);
            }
            // h1 = tanh(d); D-fragment == stage-2 A-fragment layout
            #pragma unroll
            for (int ks = 0; ks < 4; ++ks) {
                #pragma unroll
                for (int hh = 0; hh < 2; ++hh) {
                    int j = 2 * ks + hh;
                    float v0 = tanh_fast(d[j][0]);
                    float v1 = tanh_fast(d[j][1]);
                    float v2 = tanh_fast(d[j][2]);
                    float v3 = tanh_fast(d[j][3]);
                    Ah[m][ks][2 * hh]     = pack_h2(v0, v1);
                    Ah[m][ks][2 * hh + 1] = pack_h2(v2, v3);
                }
            }
        }

        // PAR: fp16 pair buffer, 32 rows x stride 20 uint32 per warp
        uint32_t* ppw = (uint32_t*)(smem + SM_PAR + w * 2560);

        // -------- per transformed feature: stage-2 mma + spline --------
        #pragma unroll 1
        for (int t = 0; t < 8; ++t) {
            #pragma unroll
            for (int j = 0; j < 4; ++j) {
                uint32_t nb = (uint32_t)(t * 32 + 8 * j) * 144u + bterm;
                uint32_t Bh[4][2];
                ldm_x4(Bh[0][0], Bh[0][1], Bh[1][0], Bh[1][1], smb + SM_BH + nb);
                ldm_x4(Bh[2][0], Bh[2][1], Bh[3][0], Bh[3][1], smb + SM_BH + nb + 64u);

                // bias for this lane's two columns (col-dependent only)
                float2 bb = *(float2*)(sbf + t * 32 + 8 * j + 2 * q);

                #pragma unroll
                for (int m = 0; m < 2; ++m) {
                    // two independent half-chains; da seeded with the bias
                    float da0 = bb.x, da1 = bb.y, da2 = bb.x, da3 = bb.y;
                    float db0 = 0.0f, db1 = 0.0f, db2 = 0.0f, db3 = 0.0f;
                    mma_f16(da0, da1, da2, da3,
                            Ah[m][0][0], Ah[m][0][1], Ah[m][0][2], Ah[m][0][3],
                            Bh[0][0], Bh[0][1]);
                    mma_f16(db0, db1, db2, db3,
                            Ah[m][2][0], Ah[m][2][1], Ah[m][2][2], Ah[m][2][3],
                            Bh[2][0], Bh[2][1]);
                    mma_f16(da0, da1, da2, da3,
                            Ah[m][1][0], Ah[m][1][1], Ah[m][1][2], Ah[m][1][3],
                            Bh[1][0], Bh[1][1]);
                    mma_f16(db0, db1, db2, db3,
                            Ah[m][3][0], Ah[m][3][1], Ah[m][3][2], Ah[m][3][3],
                            Bh[3][0], Bh[3][1]);
                    // pack to fp16 pairs, scatter (stride 20 -> conflict-free)
                    ppw[(16 * m + g) * 20 + 4 * j + q]     = pack_h2(da0 + db0, da1 + db1);
                    ppw[(16 * m + 8 + g) * 20 + 4 * j + q] = pack_h2(da2 + db2, da3 + db3);
                }
            }
            __syncwarp();

            // gather this thread's row params (bias folded; cols = 2*pairidx)
            float acc[25];
            {
                const uint32_t* pr = ppw + lane * 20;
                #pragma unroll
                for (int s = 0; s < 6; ++s) {
                    uint2 v = *(const uint2*)(pr + 2 * s);
                    float2 f0 = __half22float2(*reinterpret_cast<const __half2*>(&v.x));
                    float2 f1 = __half22float2(*reinterpret_cast<const __half2*>(&v.y));
                    acc[4 * s + 0] = f0.x; acc[4 * s + 1] = f0.y;
                    acc[4 * s + 2] = f1.x; acc[4 * s + 3] = f1.y;
                }
                uint32_t v24 = pr[12];
                acc[24] = __low2float(*reinterpret_cast<const __half2*>(&v24));
            }
            __syncwarp();   // params buffer free for next feature

            // ---- RQ spline forward + log-det ----
            float xv = par ? zb[t] : za[t];

            float mw = acc[0];
            #pragma unroll
            for (int k = 1; k < 8; ++k) mw = fmaxf(mw, acc[k]);
            float ew[8]; float swsum = 0.0f;
            #pragma unroll
            for (int k = 0; k < 8; ++k) { ew[k] = __expf(acc[k] - mw); swsum += ew[k]; }
            float cw = __fdividef(19.9992f, swsum);

            float mh = acc[8];
            #pragma unroll
            for (int k = 1; k < 8; ++k) mh = fmaxf(mh, acc[8 + k]);
            float eh[8]; float shsum = 0.0f;
            #pragma unroll
            for (int k = 0; k < 8; ++k) { eh[k] = __expf(acc[8 + k] - mh); shsum += eh[k]; }
            float chh = __fdividef(19.9992f, shsum);

            float cum = -10.0f, xk = -10.0f;
            int idx = 0;
            #pragma unroll
            for (int k = 0; k < 7; ++k) {
                cum += ew[k] * cw + 1e-4f;
                if (xv >= cum) { xk = cum; idx = k + 1; }
            }

            float yk = -10.0f, bh = 0.0f, bw = 1.0f, udk = 0.0f, udk1 = 0.0f;
            #pragma unroll
            for (int k = 0; k < 8; ++k) {
                float hh = eh[k] * chh + 1e-4f;
                if (k < idx) yk += hh;
                if (k == idx) {
                    bh = hh;
                    bw = ew[k] * cw + 1e-4f;
                    udk = acc[16 + k];
                    udk1 = acc[17 + k];
                }
            }

            float dk  = softplus_f(udk  + 0.54116665f) + 1e-4f;
            float dk1 = softplus_f(udk1 + 0.54116665f) + 1e-4f;
            float s   = __fdividef(bh, bw);
            float zt  = __saturatef(__fdividef(xv - xk, bw));
            float z1  = 1.0f - zt;
            float zz  = zt * zt;
            float zz1 = zt * z1;
            float den = s + (dk1 + dk - 2.0f * s) * zz1;
            float rden = __fdividef(1.0f, den);
            float y   = yk + bh * (s * zz + dk * zz1) * rden;
            float numld = dk1 * zz + 2.0f * s * zz1 + dk * z1 * z1;
            // ld = 2log(s) + log(numld) - 2log(den), folded to one log
            float ld = __logf(s * s * numld * rden * rden);

            bool outside = (xv <= -10.0f) || (xv >= 10.0f);
            if (outside) { y = xv; ld = 0.0f; }

            if (par) zb[t] = y; else za[t] = y;
            logdet += ld;
        }

        // -------- affine: z = z*scale + shift --------
        #pragma unroll
        for (int t = 0; t < 8; ++t) {
            za[t] = za[t] * ssc[2 * t]     + ssh[2 * t];
            zb[t] = zb[t] * ssc[2 * t + 1] + ssh[2 * t + 1];
        }
        logdet += g_lc[l];
    }

    float ss = 0.0f;
    #pragma unroll
    for (int t = 0; t < 8; ++t) ss += za[t] * za[t] + zb[t] * zb[t];

    if (valid) out[row] = -0.5f * ss - 14.703170f + logdet;   // 8*log(2*pi)
}

extern "C" void kernel_launch(void* const* d_in, const int* in_sizes, int n_in,
                              void* d_out, int out_size) {
    const float* x     = (const float*)d_in[0];
    const float* W0    = (const float*)d_in[1];
    const float* b0    = (const float*)d_in[2];
    const float* W1    = (const float*)d_in[3];
    const float* b1    = (const float*)d_in[4];
    const float* W2    = (const float*)d_in[5];
    const float* b2    = (const float*)d_in[6];
    const float* Wout  = (const float*)d_in[7];
    const float* bout  = (const float*)d_in[8];
    const float* scale = (const float*)d_in[9];
    const float* shift = (const float*)d_in[10];

    int B = in_sizes[0] / 16;

    const int NP = 8 * 256 * 64 + 8 * 256 + 8 + 8 * 64 * 16;
    precompute_kernel<<<(NP + 255) / 256, 256>>>(W1, W2, b2, Wout, bout, scale);

    cudaFuncSetAttribute(flow_kernel, cudaFuncAttributeMaxDynamicSharedMemorySize, SM_TOTAL);
    flow_kernel<<<(B + BLK - 1) / BLK, BLK, SM_TOTAL>>>(
        x, W0, b0, b1, scale, shift, (float*)d_out, B);
}